// round 1
// baseline (speedup 1.0000x reference)
#include <cuda_runtime.h>

#define NN 100000
#define NE 1600000
#define FH 128
#define FO 40

// ---------------- scratch (device globals; no allocation allowed) ----------
__device__ int   g_deg[NN];
__device__ float g_dinv[NN];
__device__ int   g_rowoff[NN + 1];
__device__ int   g_cursor[NN];
__device__ int   g_csr[NE];
__device__ float g_H0[(size_t)NN * FH];
__device__ float g_H1[(size_t)NN * FH];
__device__ float g_B1[(size_t)NN * FH];
__device__ float g_B2[(size_t)NN * FH];

// ---------------- graph preprocessing ----------------
__global__ void k_zero_deg() {
    int i = blockIdx.x * blockDim.x + threadIdx.x;
    if (i < NN) g_deg[i] = 0;
}

__global__ void k_hist(const int* __restrict__ dst) {
    int e = blockIdx.x * blockDim.x + threadIdx.x;
    if (e < NE) atomicAdd(&g_deg[dst[e]], 1);
}

__global__ void k_dinv() {
    int i = blockIdx.x * blockDim.x + threadIdx.x;
    if (i < NN) {
        int d = g_deg[i];
        float df = (float)(d > 1 ? d : 1);
        g_dinv[i] = rsqrtf(df);
    }
}

// Single-block scan of g_deg -> exclusive prefix into g_rowoff.
__global__ void __launch_bounds__(1024) k_scan() {
    __shared__ int wsum[32];
    __shared__ int s_carry;
    const int t = threadIdx.x, lane = t & 31, wp = t >> 5;
    if (t == 0) s_carry = 0;
    __syncthreads();
    for (int base = 0; base < NN; base += 1024) {
        int i = base + t;
        int v = (i < NN) ? g_deg[i] : 0;
        int x = v;
        #pragma unroll
        for (int o = 1; o < 32; o <<= 1) {
            int y = __shfl_up_sync(0xffffffffu, x, o);
            if (lane >= o) x += y;
        }
        if (lane == 31) wsum[wp] = x;
        __syncthreads();
        if (wp == 0) {
            int s = wsum[lane];
            #pragma unroll
            for (int o = 1; o < 32; o <<= 1) {
                int y = __shfl_up_sync(0xffffffffu, s, o);
                if (lane >= o) s += y;
            }
            wsum[lane] = s;
        }
        __syncthreads();
        int off = s_carry + (wp ? wsum[wp - 1] : 0);
        if (i < NN) g_rowoff[i] = off + x - v;
        int tile_total = wsum[31];
        __syncthreads();
        if (t == 1023) s_carry = s_carry + tile_total;
        __syncthreads();
    }
    if (t == 0) g_rowoff[NN] = NE;
}

__global__ void k_cursor() {
    int i = blockIdx.x * blockDim.x + threadIdx.x;
    if (i < NN) g_cursor[i] = g_rowoff[i];
}

__global__ void k_scatter(const int* __restrict__ src, const int* __restrict__ dst) {
    int e = blockIdx.x * blockDim.x + threadIdx.x;
    if (e < NE) {
        int p = atomicAdd(&g_cursor[dst[e]], 1);
        g_csr[p] = src[e];
    }
}

// ---------------- SpMM: warp-per-node, CSR gather (no atomics) ----------------
// MODE 1: out = -dinv[v] * sum_{s in N(v)} Y[s]*dinv[s]          (X1 = -spmm(X0))
// MODE 2: out = -2*dinv[v]*sum(...) - X0[v]                      (X2 = -2*spmm(X1) - X0)
template <int MODE>
__global__ void __launch_bounds__(256) k_spmm(const float* __restrict__ Y,
                                              const float* __restrict__ X0,
                                              float* __restrict__ out) {
    int w = (blockIdx.x * blockDim.x + threadIdx.x) >> 5;
    int lane = threadIdx.x & 31;
    if (w >= NN) return;
    int beg = g_rowoff[w];
    int end = g_rowoff[w + 1];
    float ax = 0.f, ay = 0.f, az = 0.f, aw = 0.f;
    for (int i = beg; i < end; ++i) {
        int s = g_csr[i];
        float ds = g_dinv[s];
        float4 y = *(const float4*)(Y + (size_t)s * FH + lane * 4);
        ax = fmaf(y.x, ds, ax);
        ay = fmaf(y.y, ds, ay);
        az = fmaf(y.z, ds, az);
        aw = fmaf(y.w, ds, aw);
    }
    float dv = g_dinv[w];
    float4 o;
    if (MODE == 1) {
        o.x = -dv * ax; o.y = -dv * ay; o.z = -dv * az; o.w = -dv * aw;
    } else {
        float4 x0 = *(const float4*)(X0 + (size_t)w * FH + lane * 4);
        float m = -2.f * dv;
        o.x = fmaf(m, ax, -x0.x);
        o.y = fmaf(m, ay, -x0.y);
        o.z = fmaf(m, az, -x0.z);
        o.w = fmaf(m, aw, -x0.w);
    }
    *(float4*)(out + (size_t)w * FH + lane * 4) = o;
}

// ---------------- fused GEMM: out = relu([X0|X1|X2] @ W + b) ----------------
// A is the virtual [N, 384] concat of the 3 bases; W is [384, CO] row-major.
template <int CO, int TM, int TN>
__global__ void k_gemm(const float* __restrict__ X0, const float* __restrict__ X1,
                       const float* __restrict__ X2, const float* __restrict__ W,
                       const float* __restrict__ bias, float* __restrict__ out) {
    constexpr int BM = 128, BK = 16;
    constexpr int NTX = CO / TN;
    constexpr int NTY = BM / TM;
    constexpr int NT  = NTX * NTY;
    __shared__ float As[BK][BM + 1];
    __shared__ float Bs[BK][CO];
    const int tid = threadIdx.x;
    const int tx = tid % NTX;
    const int ty = tid / NTX;
    const int rowBase = blockIdx.x * BM;

    float acc[TM][TN];
    #pragma unroll
    for (int m = 0; m < TM; ++m)
        #pragma unroll
        for (int n = 0; n < TN; ++n) acc[m][n] = 0.f;

    #pragma unroll 1
    for (int kt = 0; kt < 24; ++kt) {
        const float* __restrict__ A = (kt < 8) ? X0 : ((kt < 16) ? X1 : X2);
        const int kcol = (kt & 7) * BK;
        // load A tile (transposed into smem)
        for (int i = tid; i < BM * BK; i += NT) {
            int r = i >> 4;
            int k = i & 15;
            int row = rowBase + r;
            As[k][r] = (row < NN) ? A[(size_t)row * FH + kcol + k] : 0.f;
        }
        // load B tile
        for (int i = tid; i < BK * CO; i += NT) {
            int k = i / CO;
            int c = i % CO;
            Bs[k][c] = W[(size_t)(kt * BK + k) * CO + c];
        }
        __syncthreads();
        #pragma unroll
        for (int k = 0; k < BK; ++k) {
            float ra[TM], rb[TN];
            #pragma unroll
            for (int m = 0; m < TM; ++m) ra[m] = As[k][ty * TM + m];
            #pragma unroll
            for (int n = 0; n < TN; ++n) rb[n] = Bs[k][tx * TN + n];
            #pragma unroll
            for (int m = 0; m < TM; ++m)
                #pragma unroll
                for (int n = 0; n < TN; ++n)
                    acc[m][n] = fmaf(ra[m], rb[n], acc[m][n]);
        }
        __syncthreads();
    }

    #pragma unroll
    for (int m = 0; m < TM; ++m) {
        int row = rowBase + ty * TM + m;
        if (row < NN) {
            #pragma unroll
            for (int n = 0; n < TN; ++n) {
                int c = tx * TN + n;
                float v = acc[m][n] + bias[c];
                out[(size_t)row * CO + c] = fmaxf(v, 0.f);
            }
        }
    }
}

// ---------------- host launcher ----------------
extern "C" void kernel_launch(void* const* d_in, const int* in_sizes, int n_in,
                              void* d_out, int out_size) {
    const float* feat = (const float*)d_in[0];
    const int*   src  = (const int*)d_in[1];
    const int*   dst  = (const int*)d_in[2];
    const float* W0   = (const float*)d_in[3];
    const float* b0   = (const float*)d_in[4];
    const float* Wh   = (const float*)d_in[5];
    const float* bh   = (const float*)d_in[6];
    const float* Wl   = (const float*)d_in[7];
    const float* bl   = (const float*)d_in[8];
    float* out = (float*)d_out;

    float *H0, *H1, *B1, *B2;
    cudaGetSymbolAddress((void**)&H0, g_H0);
    cudaGetSymbolAddress((void**)&H1, g_H1);
    cudaGetSymbolAddress((void**)&B1, g_B1);
    cudaGetSymbolAddress((void**)&B2, g_B2);

    const int TPB = 256;
    const int nodeBlocks = (NN + TPB - 1) / TPB;
    const int edgeBlocks = (NE + TPB - 1) / TPB;

    // --- build dinv + CSR (dst-major) ---
    k_zero_deg<<<nodeBlocks, TPB>>>();
    k_hist<<<edgeBlocks, TPB>>>(dst);
    k_dinv<<<nodeBlocks, TPB>>>();
    k_scan<<<1, 1024>>>();
    k_cursor<<<nodeBlocks, TPB>>>();
    k_scatter<<<edgeBlocks, TPB>>>(src, dst);

    const int spmmBlocks = (NN * 32 + TPB - 1) / TPB;  // warp per node
    const int gemmBlocks = (NN + 127) / 128;

    const float* cur = feat;
    float* bufs[2] = {H0, H1};
    for (int layer = 0; layer < 7; ++layer) {
        k_spmm<1><<<spmmBlocks, TPB>>>(cur, nullptr, B1);
        k_spmm<2><<<spmmBlocks, TPB>>>(B1, cur, B2);
        if (layer < 6) {
            const float* W;
            const float* b;
            if (layer == 0) { W = W0; b = b0; }
            else            { W = Wh + (size_t)(layer - 1) * 384 * 128; b = bh + (layer - 1) * 128; }
            float* o = bufs[layer & 1];
            k_gemm<128, 8, 8><<<gemmBlocks, 256>>>(cur, B1, B2, W, b, o);
            cur = o;
        } else {
            k_gemm<40, 8, 5><<<gemmBlocks, 128>>>(cur, B1, B2, Wl, bl, out);
        }
    }
}

// round 3
// speedup vs baseline: 1.5649x; 1.5649x over previous
#include <cuda_runtime.h>
#include <cuda_bf16.h>
#include <cstdint>

#define NN 100000
#define NE 1600000
#define FH 128
#define FO 40

// ======================= device scratch (no allocs allowed) =======================
__device__ int   g_deg[NN];
__device__ float g_dinv[NN];
__device__ int   g_rowoff[NN + 1];
__device__ int   g_cursor[NN];
__device__ int   g_csr[NE];
__device__ int   g_bsum[128];
__device__ int   g_boff[128];

__device__ float g_H[2][(size_t)NN * FH];     // GEMM fp32 outputs (ping-pong)
__device__ float g_B1f[(size_t)NN * FH];      // X1 fp32 (spmm2 input)
__device__ float g_B2f[(size_t)NN * FH];      // X2 fp32 (final SIMT layer only)
__device__ __nv_bfloat16 g_X0h[2][(size_t)NN * FH];
__device__ __nv_bfloat16 g_X0l[2][(size_t)NN * FH];
__device__ __nv_bfloat16 g_B1h[(size_t)NN * FH];
__device__ __nv_bfloat16 g_B1l[(size_t)NN * FH];
__device__ __nv_bfloat16 g_B2h[(size_t)NN * FH];
__device__ __nv_bfloat16 g_B2l[(size_t)NN * FH];
__device__ __nv_bfloat16 g_Wth[6 * 128 * 384];   // W^T per layer: [n=128][k=384], hi
__device__ __nv_bfloat16 g_Wtl[6 * 128 * 384];   // lo

// ======================= helpers =======================
__device__ __forceinline__ uint32_t smem_u32(const void* p) {
    uint32_t a;
    asm("{ .reg .u64 t; cvta.to.shared.u64 t, %1; cvt.u32.u64 %0, t; }" : "=r"(a) : "l"(p));
    return a;
}

#define SWZ(off) ((off) ^ (((off) >> 3) & 0x70))

__device__ __forceinline__ void ldmx4(uint32_t* r, uint32_t addr) {
    asm volatile("ldmatrix.sync.aligned.m8n8.x4.shared.b16 {%0,%1,%2,%3}, [%4];"
                 : "=r"(r[0]), "=r"(r[1]), "=r"(r[2]), "=r"(r[3]) : "r"(addr));
}

__device__ __forceinline__ void mma_bf16(float* d, const uint32_t* a, const uint32_t* b) {
    asm volatile(
        "mma.sync.aligned.m16n8k16.row.col.f32.bf16.bf16.f32 "
        "{%0,%1,%2,%3}, {%4,%5,%6,%7}, {%8,%9}, {%0,%1,%2,%3};"
        : "+f"(d[0]), "+f"(d[1]), "+f"(d[2]), "+f"(d[3])
        : "r"(a[0]), "r"(a[1]), "r"(a[2]), "r"(a[3]), "r"(b[0]), "r"(b[1]));
}

__device__ __forceinline__ uint32_t pack_hi2(float a, float b) {
    __nv_bfloat16 ha = __float2bfloat16(a), hb = __float2bfloat16(b);
    return (uint32_t)__bfloat16_as_ushort(ha) | ((uint32_t)__bfloat16_as_ushort(hb) << 16);
}
__device__ __forceinline__ uint32_t pack_lo2(float a, float b) {
    __nv_bfloat16 ha = __float2bfloat16(a), hb = __float2bfloat16(b);
    __nv_bfloat16 la = __float2bfloat16(a - __bfloat162float(ha));
    __nv_bfloat16 lb = __float2bfloat16(b - __bfloat162float(hb));
    return (uint32_t)__bfloat16_as_ushort(la) | ((uint32_t)__bfloat16_as_ushort(lb) << 16);
}

// ======================= graph preprocessing =======================
__global__ void k_zero_deg() {
    int i = blockIdx.x * blockDim.x + threadIdx.x;
    if (i < NN) g_deg[i] = 0;
}
__global__ void k_hist(const int* __restrict__ dst) {
    int e = blockIdx.x * blockDim.x + threadIdx.x;
    if (e < NE) atomicAdd(&g_deg[dst[e]], 1);
}
__global__ void k_dinv() {
    int i = blockIdx.x * blockDim.x + threadIdx.x;
    if (i < NN) {
        int d = g_deg[i];
        g_dinv[i] = rsqrtf((float)(d > 1 ? d : 1));
    }
}

__global__ void __launch_bounds__(1024) k_scanA() {
    __shared__ int wsum[32];
    int t = threadIdx.x, lane = t & 31, wp = t >> 5;
    int i = blockIdx.x * 1024 + t;
    int v = (i < NN) ? g_deg[i] : 0;
    int x = v;
    #pragma unroll
    for (int o = 1; o < 32; o <<= 1) {
        int y = __shfl_up_sync(0xffffffffu, x, o);
        if (lane >= o) x += y;
    }
    if (lane == 31) wsum[wp] = x;
    __syncthreads();
    if (wp == 0) {
        int s = wsum[lane];
        #pragma unroll
        for (int o = 1; o < 32; o <<= 1) {
            int y = __shfl_up_sync(0xffffffffu, s, o);
            if (lane >= o) s += y;
        }
        wsum[lane] = s;
    }
    __syncthreads();
    int off = (wp ? wsum[wp - 1] : 0);
    if (i < NN) g_rowoff[i] = off + x - v;
    if (t == 1023) g_bsum[blockIdx.x] = wsum[31];
}

__global__ void k_scanB(int nb) {
    __shared__ int sh[4];
    int t = threadIdx.x, lane = t & 31, wp = t >> 5;
    int v = (t < nb) ? g_bsum[t] : 0;
    int x = v;
    #pragma unroll
    for (int o = 1; o < 32; o <<= 1) {
        int y = __shfl_up_sync(0xffffffffu, x, o);
        if (lane >= o) x += y;
    }
    if (lane == 31) sh[wp] = x;
    __syncthreads();
    int add = 0;
    for (int w = 0; w < wp; ++w) add += sh[w];
    if (t < 128) g_boff[t] = add + x - v;
}

__global__ void k_scanC() {
    int i = blockIdx.x * blockDim.x + threadIdx.x;
    if (i < NN) {
        int r = g_rowoff[i] + g_boff[i >> 10];
        g_rowoff[i] = r;
        g_cursor[i] = r;
    }
    if (i == 0) g_rowoff[NN] = NE;
}

__global__ void k_scatter(const int* __restrict__ src, const int* __restrict__ dst) {
    int e = blockIdx.x * blockDim.x + threadIdx.x;
    if (e < NE) {
        int p = atomicAdd(&g_cursor[dst[e]], 1);
        g_csr[p] = src[e];
    }
}

// ======================= input conversion =======================
__global__ void k_featsplit(const float* __restrict__ f) {
    size_t i = ((size_t)blockIdx.x * blockDim.x + threadIdx.x) * 4;
    if (i >= (size_t)NN * FH) return;
    float4 v = *(const float4*)(f + i);
    uint2 h, l;
    h.x = pack_hi2(v.x, v.y); h.y = pack_hi2(v.z, v.w);
    l.x = pack_lo2(v.x, v.y); l.y = pack_lo2(v.z, v.w);
    *(uint2*)(&g_X0h[0][i]) = h;
    *(uint2*)(&g_X0l[0][i]) = l;
}

__global__ void k_prep_w(const float* __restrict__ W0, const float* __restrict__ Wh) {
    int i = blockIdx.x * blockDim.x + threadIdx.x;
    if (i >= 6 * 384 * 128) return;
    int l = i / (384 * 128);
    int r = i % (384 * 128);
    int k = r / 128, n = r % 128;
    const float* W = (l == 0) ? W0 : (Wh + (size_t)(l - 1) * 384 * 128);
    float v = W[(size_t)k * 128 + n];
    __nv_bfloat16 h = __float2bfloat16(v);
    float lo = v - __bfloat162float(h);
    size_t o = (size_t)l * 128 * 384 + (size_t)n * 384 + k;
    g_Wth[o] = h;
    g_Wtl[o] = __float2bfloat16(lo);
}

// ======================= SpMM: warp-per-node CSR gather =======================
template <int MODE, bool WF32, bool WBF>
__global__ void __launch_bounds__(256) k_spmm(const float* __restrict__ Y,
                                              const float* __restrict__ X0,
                                              float* __restrict__ outf,
                                              __nv_bfloat16* __restrict__ oh,
                                              __nv_bfloat16* __restrict__ ol) {
    int w = (blockIdx.x * blockDim.x + threadIdx.x) >> 5;
    int lane = threadIdx.x & 31;
    if (w >= NN) return;
    int beg = g_rowoff[w];
    int end = g_rowoff[w + 1];
    float ax = 0.f, ay = 0.f, az = 0.f, aw = 0.f;
    for (int i = beg; i < end; ++i) {
        int s = g_csr[i];
        float ds = g_dinv[s];
        float4 y = *(const float4*)(Y + (size_t)s * FH + lane * 4);
        ax = fmaf(y.x, ds, ax);
        ay = fmaf(y.y, ds, ay);
        az = fmaf(y.z, ds, az);
        aw = fmaf(y.w, ds, aw);
    }
    float dv = g_dinv[w];
    float4 o;
    if (MODE == 1) {
        o.x = -dv * ax; o.y = -dv * ay; o.z = -dv * az; o.w = -dv * aw;
    } else {
        float4 x0 = *(const float4*)(X0 + (size_t)w * FH + lane * 4);
        float m = -2.f * dv;
        o.x = fmaf(m, ax, -x0.x);
        o.y = fmaf(m, ay, -x0.y);
        o.z = fmaf(m, az, -x0.z);
        o.w = fmaf(m, aw, -x0.w);
    }
    size_t base = (size_t)w * FH + lane * 4;
    if (WF32) *(float4*)(outf + base) = o;
    if (WBF) {
        uint2 h, l;
        h.x = pack_hi2(o.x, o.y); h.y = pack_hi2(o.z, o.w);
        l.x = pack_lo2(o.x, o.y); l.y = pack_lo2(o.z, o.w);
        *(uint2*)(oh + base) = h;
        *(uint2*)(ol + base) = l;
    }
}

// ======================= mma.sync bf16-pair GEMM =======================
// C[128-tile, 128] = relu( [X0|X1|X2](fp32 as hi+lo bf16) @ W + b )
// 512 threads, 4x4 warp grid, 32x32 warp tiles, K-chunks of 64, 3 passes (hh+hl+lh).
#define GM_OFF_A_HI 0
#define GM_OFF_A_LO 16384
#define GM_OFF_B_HI 32768
#define GM_OFF_B_LO 49152
#define GM_SMEM_SZ  (65536 + 1024)

__global__ void __launch_bounds__(512) k_gemm_mma(
    const __nv_bfloat16* __restrict__ x0h, const __nv_bfloat16* __restrict__ x0l,
    const float* __restrict__ bias,
    const __nv_bfloat16* __restrict__ wth, const __nv_bfloat16* __restrict__ wtl,
    float* __restrict__ outf,
    __nv_bfloat16* __restrict__ outh, __nv_bfloat16* __restrict__ outl) {
    extern __shared__ char smem_raw[];
    __shared__ float s_bias[128];
    uint32_t sb0 = smem_u32(smem_raw);
    uint32_t sb = (sb0 + 1023u) & ~1023u;          // 1024B-align for SW128
    char* smem = smem_raw + (sb - sb0);

    const int tid = threadIdx.x, lane = tid & 31, wid = tid >> 5;
    const int wm = wid >> 2, wn = wid & 3;         // 4x4 warp grid
    const int rowBase = blockIdx.x * 128;
    if (tid < 128) s_bias[tid] = bias[tid];

    const __nv_bfloat16* Ah[3] = {x0h, g_B1h, g_B2h};
    const __nv_bfloat16* Al[3] = {x0l, g_B1l, g_B2l};

    float acc[2][4][4];
    #pragma unroll
    for (int a = 0; a < 2; ++a)
        #pragma unroll
        for (int b = 0; b < 4; ++b)
            #pragma unroll
            for (int c = 0; c < 4; ++c) acc[a][b][c] = 0.f;

    const int lrow = lane & 7, seg = lane >> 3;

    #pragma unroll 1
    for (int kc = 0; kc < 6; ++kc) {
        const __nv_bfloat16* __restrict__ ah = Ah[kc >> 1];
        const __nv_bfloat16* __restrict__ al = Al[kc >> 1];
        const int coff = (kc & 1) * 64;
        // ---- load A tiles: 128 rows x 64 bf16 (128B rows, SW128) ----
        #pragma unroll
        for (int t = 0; t < 2; ++t) {
            int idx = tid + t * 512;
            int r = idx >> 3, j = idx & 7;
            int row = rowBase + r;
            uint32_t sw = SWZ((uint32_t)(r * 128 + j * 16));
            uint4 vh = make_uint4(0, 0, 0, 0), vl = make_uint4(0, 0, 0, 0);
            if (row < NN) {
                vh = *((const uint4*)(ah + (size_t)row * FH + coff) + j);
                vl = *((const uint4*)(al + (size_t)row * FH + coff) + j);
            }
            *(uint4*)(smem + GM_OFF_A_HI + sw) = vh;
            *(uint4*)(smem + GM_OFF_A_LO + sw) = vl;
        }
        // ---- load B tiles: 128 n-rows x 64 bf16 from W^T ----
        #pragma unroll
        for (int t = 0; t < 2; ++t) {
            int idx = tid + t * 512;
            int n = idx >> 3, j = idx & 7;
            uint32_t sw = SWZ((uint32_t)(n * 128 + j * 16));
            *(uint4*)(smem + GM_OFF_B_HI + sw) = *((const uint4*)(wth + (size_t)n * 384 + kc * 64) + j);
            *(uint4*)(smem + GM_OFF_B_LO + sw) = *((const uint4*)(wtl + (size_t)n * 384 + kc * 64) + j);
        }
        __syncthreads();

        // ---- compute: 4 k16 steps ----
        #pragma unroll
        for (int kt = 0; kt < 4; ++kt) {
            uint32_t Ahf[2][4], Alf[2][4], Bhf[2][4], Blf[2][4];
            #pragma unroll
            for (int mt = 0; mt < 2; ++mt) {
                int m = wm * 32 + mt * 16 + (seg & 1) * 8 + lrow;
                int kb = kt * 32 + (seg >> 1) * 16;
                uint32_t sw = SWZ((uint32_t)(m * 128 + kb));
                ldmx4(Ahf[mt], sb + GM_OFF_A_HI + sw);
                ldmx4(Alf[mt], sb + GM_OFF_A_LO + sw);
            }
            #pragma unroll
            for (int ntp = 0; ntp < 2; ++ntp) {
                int n = wn * 32 + ntp * 16 + (seg >> 1) * 8 + lrow;
                int kb = kt * 32 + (seg & 1) * 16;
                uint32_t sw = SWZ((uint32_t)(n * 128 + kb));
                ldmx4(Bhf[ntp], sb + GM_OFF_B_HI + sw);
                ldmx4(Blf[ntp], sb + GM_OFF_B_LO + sw);
            }
            #pragma unroll
            for (int mt = 0; mt < 2; ++mt)
                #pragma unroll
                for (int ntp = 0; ntp < 2; ++ntp)
                    #pragma unroll
                    for (int sub = 0; sub < 2; ++sub) {
                        int nj = ntp * 2 + sub;
                        mma_bf16(acc[mt][nj], Ahf[mt], &Bhf[ntp][sub * 2]);
                        mma_bf16(acc[mt][nj], Ahf[mt], &Blf[ntp][sub * 2]);
                        mma_bf16(acc[mt][nj], Alf[mt], &Bhf[ntp][sub * 2]);
                    }
        }
        __syncthreads();
    }

    // ---- epilogue: bias + relu; write fp32 + bf16 hi/lo ----
    #pragma unroll
    for (int mt = 0; mt < 2; ++mt) {
        #pragma unroll
        for (int nj = 0; nj < 4; ++nj) {
            int col = wn * 32 + nj * 8 + (lane & 3) * 2;
            float bz0 = s_bias[col], bz1 = s_bias[col + 1];
            #pragma unroll
            for (int rp = 0; rp < 2; ++rp) {
                int row = rowBase + wm * 32 + mt * 16 + (lane >> 2) + rp * 8;
                if (row < NN) {
                    float v0 = fmaxf(acc[mt][nj][rp * 2 + 0] + bz0, 0.f);
                    float v1 = fmaxf(acc[mt][nj][rp * 2 + 1] + bz1, 0.f);
                    size_t base = (size_t)row * FH + col;
                    *(float2*)(outf + base) = make_float2(v0, v1);
                    *(uint32_t*)(outh + base) = pack_hi2(v0, v1);
                    *(uint32_t*)(outl + base) = pack_lo2(v0, v1);
                }
            }
        }
    }
}

// ======================= SIMT GEMM for final layer (CO=40) =======================
template <int CO, int TM, int TN>
__global__ void k_gemm_simt(const float* __restrict__ X0, const float* __restrict__ X1,
                            const float* __restrict__ X2, const float* __restrict__ W,
                            const float* __restrict__ bias, float* __restrict__ out) {
    constexpr int BM = 128, BK = 16;
    constexpr int NTX = CO / TN;
    constexpr int NTY = BM / TM;
    constexpr int NT = NTX * NTY;
    __shared__ float As[BK][BM + 1];
    __shared__ float Bs[BK][CO];
    const int tid = threadIdx.x;
    const int tx = tid % NTX;
    const int ty = tid / NTX;
    const int rowBase = blockIdx.x * BM;

    float acc[TM][TN];
    #pragma unroll
    for (int m = 0; m < TM; ++m)
        #pragma unroll
        for (int n = 0; n < TN; ++n) acc[m][n] = 0.f;

    #pragma unroll 1
    for (int kt = 0; kt < 24; ++kt) {
        const float* __restrict__ A = (kt < 8) ? X0 : ((kt < 16) ? X1 : X2);
        const int kcol = (kt & 7) * BK;
        for (int i = tid; i < BM * BK; i += NT) {
            int r = i >> 4, k = i & 15;
            int row = rowBase + r;
            As[k][r] = (row < NN) ? A[(size_t)row * FH + kcol + k] : 0.f;
        }
        for (int i = tid; i < BK * CO; i += NT) {
            int k = i / CO, c = i % CO;
            Bs[k][c] = W[(size_t)(kt * BK + k) * CO + c];
        }
        __syncthreads();
        #pragma unroll
        for (int k = 0; k < BK; ++k) {
            float ra[TM], rb[TN];
            #pragma unroll
            for (int m = 0; m < TM; ++m) ra[m] = As[k][ty * TM + m];
            #pragma unroll
            for (int n = 0; n < TN; ++n) rb[n] = Bs[k][tx * TN + n];
            #pragma unroll
            for (int m = 0; m < TM; ++m)
                #pragma unroll
                for (int n = 0; n < TN; ++n)
                    acc[m][n] = fmaf(ra[m], rb[n], acc[m][n]);
        }
        __syncthreads();
    }
    #pragma unroll
    for (int m = 0; m < TM; ++m) {
        int row = rowBase + ty * TM + m;
        if (row < NN) {
            #pragma unroll
            for (int n = 0; n < TN; ++n) {
                int c = tx * TN + n;
                out[(size_t)row * CO + c] = fmaxf(acc[m][n] + bias[c], 0.f);
            }
        }
    }
}

// ======================= host launcher =======================
extern "C" void kernel_launch(void* const* d_in, const int* in_sizes, int n_in,
                              void* d_out, int out_size) {
    const float* feat = (const float*)d_in[0];
    const int*   src  = (const int*)d_in[1];
    const int*   dst  = (const int*)d_in[2];
    const float* W0   = (const float*)d_in[3];
    const float* b0   = (const float*)d_in[4];
    const float* Wh   = (const float*)d_in[5];
    const float* bh   = (const float*)d_in[6];
    const float* Wl   = (const float*)d_in[7];
    const float* bl   = (const float*)d_in[8];
    float* out = (float*)d_out;

    float *H, *B1f, *B2f;
    __nv_bfloat16 *X0h, *X0l, *B1h, *B1l, *B2h, *B2l, *Wth, *Wtl;
    cudaGetSymbolAddress((void**)&H,   g_H);
    cudaGetSymbolAddress((void**)&B1f, g_B1f);
    cudaGetSymbolAddress((void**)&B2f, g_B2f);
    cudaGetSymbolAddress((void**)&X0h, g_X0h);
    cudaGetSymbolAddress((void**)&X0l, g_X0l);
    cudaGetSymbolAddress((void**)&B1h, g_B1h);
    cudaGetSymbolAddress((void**)&B1l, g_B1l);
    cudaGetSymbolAddress((void**)&B2h, g_B2h);
    cudaGetSymbolAddress((void**)&B2l, g_B2l);
    cudaGetSymbolAddress((void**)&Wth, g_Wth);
    cudaGetSymbolAddress((void**)&Wtl, g_Wtl);

    cudaFuncSetAttribute(k_gemm_mma, cudaFuncAttributeMaxDynamicSharedMemorySize, GM_SMEM_SZ);

    const int TPB = 256;
    const int nodeBlocks = (NN + TPB - 1) / TPB;
    const int edgeBlocks = (NE + TPB - 1) / TPB;
    const int scanBlocks = (NN + 1023) / 1024;   // 98

    // preprocessing
    k_zero_deg<<<nodeBlocks, TPB>>>();
    k_hist<<<edgeBlocks, TPB>>>(dst);
    k_dinv<<<nodeBlocks, TPB>>>();
    k_scanA<<<scanBlocks, 1024>>>();
    k_scanB<<<1, 128>>>(scanBlocks);
    k_scanC<<<nodeBlocks, TPB>>>();
    k_scatter<<<edgeBlocks, TPB>>>(src, dst);

    // input conversion
    k_featsplit<<<(NN * FH / 4 + TPB - 1) / TPB, TPB>>>(feat);
    k_prep_w<<<(6 * 384 * 128 + TPB - 1) / TPB, TPB>>>(W0, Wh);

    const size_t SL = (size_t)NN * FH;
    const int spmmBlocks = (NN * 32 + TPB - 1) / TPB;
    const int tileBlocks = (NN + 127) / 128;

    const float* curf = feat;
    for (int l = 0; l < 6; ++l) {
        k_spmm<1, true, true><<<spmmBlocks, TPB>>>(curf, nullptr, B1f, B1h, B1l);
        k_spmm<2, false, true><<<spmmBlocks, TPB>>>(B1f, curf, nullptr, B2h, B2l);
        const float* bias = (l == 0) ? b0 : (bh + (size_t)(l - 1) * 128);
        k_gemm_mma<<<tileBlocks, 512, GM_SMEM_SZ>>>(
            X0h + (size_t)(l & 1) * SL, X0l + (size_t)(l & 1) * SL,
            bias, Wth + (size_t)l * 128 * 384, Wtl + (size_t)l * 128 * 384,
            H + (size_t)(l & 1) * SL,
            X0h + (size_t)((l + 1) & 1) * SL, X0l + (size_t)((l + 1) & 1) * SL);
        curf = H + (size_t)(l & 1) * SL;
    }
    // final layer: fp32 SIMT (CO=40)
    k_spmm<1, true, false><<<spmmBlocks, TPB>>>(curf, nullptr, B1f, nullptr, nullptr);
    k_spmm<2, true, false><<<spmmBlocks, TPB>>>(B1f, curf, B2f, nullptr, nullptr);
    k_gemm_simt<FO, 8, 5><<<tileBlocks, 128>>>(curf, B1f, B2f, Wl, bl, out);
}

// round 4
// speedup vs baseline: 1.6035x; 1.0246x over previous
#include <cuda_runtime.h>
#include <cuda_bf16.h>
#include <cstdint>

#define NN 100000
#define NE 1600000
#define FH 128
#define FO 40

// ======================= device scratch (no allocs allowed) =======================
__device__ int   g_deg[NN];
__device__ float g_dinv[NN];
__device__ float g_rdinv[NN];
__device__ int   g_rowoff[NN + 1];
__device__ int   g_cursor[NN];
__device__ int   g_csr[NE];
__device__ int   g_bsum[128];
__device__ int   g_boff[128];

__device__ float g_Hpre[2][(size_t)NN * FH];  // prescaled (x*dinv) fp32 activations (ping-pong)
__device__ float g_B1pre[(size_t)NN * FH];    // X1 prescaled fp32 (spmm2 gather source)
__device__ float g_B1f[(size_t)NN * FH];      // X1 unscaled fp32 (final layer only)
__device__ float g_B2f[(size_t)NN * FH];      // X2 unscaled fp32 (final layer only)
__device__ __nv_bfloat16 g_X0h[2][(size_t)NN * FH];
__device__ __nv_bfloat16 g_X0l[2][(size_t)NN * FH];
__device__ __nv_bfloat16 g_B1h[(size_t)NN * FH];
__device__ __nv_bfloat16 g_B1l[(size_t)NN * FH];
__device__ __nv_bfloat16 g_B2h[(size_t)NN * FH];
__device__ __nv_bfloat16 g_B2l[(size_t)NN * FH];
__device__ __nv_bfloat16 g_Wth[6 * 128 * 384];   // W^T per layer: [n=128][k=384], hi
__device__ __nv_bfloat16 g_Wtl[6 * 128 * 384];   // lo

// ======================= helpers =======================
__device__ __forceinline__ uint32_t smem_u32(const void* p) {
    uint32_t a;
    asm("{ .reg .u64 t; cvta.to.shared.u64 t, %1; cvt.u32.u64 %0, t; }" : "=r"(a) : "l"(p));
    return a;
}

#define SWZ(off) ((off) ^ (((off) >> 3) & 0x70))

__device__ __forceinline__ void ldmx4(uint32_t* r, uint32_t addr) {
    asm volatile("ldmatrix.sync.aligned.m8n8.x4.shared.b16 {%0,%1,%2,%3}, [%4];"
                 : "=r"(r[0]), "=r"(r[1]), "=r"(r[2]), "=r"(r[3]) : "r"(addr));
}

__device__ __forceinline__ void mma_bf16(float* d, const uint32_t* a, const uint32_t* b) {
    asm volatile(
        "mma.sync.aligned.m16n8k16.row.col.f32.bf16.bf16.f32 "
        "{%0,%1,%2,%3}, {%4,%5,%6,%7}, {%8,%9}, {%0,%1,%2,%3};"
        : "+f"(d[0]), "+f"(d[1]), "+f"(d[2]), "+f"(d[3])
        : "r"(a[0]), "r"(a[1]), "r"(a[2]), "r"(a[3]), "r"(b[0]), "r"(b[1]));
}

__device__ __forceinline__ uint32_t pack_hi2(float a, float b) {
    __nv_bfloat16 ha = __float2bfloat16(a), hb = __float2bfloat16(b);
    return (uint32_t)__bfloat16_as_ushort(ha) | ((uint32_t)__bfloat16_as_ushort(hb) << 16);
}
__device__ __forceinline__ uint32_t pack_lo2(float a, float b) {
    __nv_bfloat16 ha = __float2bfloat16(a), hb = __float2bfloat16(b);
    __nv_bfloat16 la = __float2bfloat16(a - __bfloat162float(ha));
    __nv_bfloat16 lb = __float2bfloat16(b - __bfloat162float(hb));
    return (uint32_t)__bfloat16_as_ushort(la) | ((uint32_t)__bfloat16_as_ushort(lb) << 16);
}

// ======================= graph preprocessing =======================
__global__ void k_zero_deg() {
    int i = blockIdx.x * blockDim.x + threadIdx.x;
    if (i < NN) g_deg[i] = 0;
}
__global__ void k_hist(const int* __restrict__ dst) {
    int e = blockIdx.x * blockDim.x + threadIdx.x;
    if (e < NE) atomicAdd(&g_deg[dst[e]], 1);
}
__global__ void k_dinv() {
    int i = blockIdx.x * blockDim.x + threadIdx.x;
    if (i < NN) {
        int d = g_deg[i];
        float df = (float)(d > 1 ? d : 1);
        float r = rsqrtf(df);
        g_dinv[i] = r;
        g_rdinv[i] = sqrtf(df);
    }
}

__global__ void __launch_bounds__(1024) k_scanA() {
    __shared__ int wsum[32];
    int t = threadIdx.x, lane = t & 31, wp = t >> 5;
    int i = blockIdx.x * 1024 + t;
    int v = (i < NN) ? g_deg[i] : 0;
    int x = v;
    #pragma unroll
    for (int o = 1; o < 32; o <<= 1) {
        int y = __shfl_up_sync(0xffffffffu, x, o);
        if (lane >= o) x += y;
    }
    if (lane == 31) wsum[wp] = x;
    __syncthreads();
    if (wp == 0) {
        int s = wsum[lane];
        #pragma unroll
        for (int o = 1; o < 32; o <<= 1) {
            int y = __shfl_up_sync(0xffffffffu, s, o);
            if (lane >= o) s += y;
        }
        wsum[lane] = s;
    }
    __syncthreads();
    int off = (wp ? wsum[wp - 1] : 0);
    if (i < NN) g_rowoff[i] = off + x - v;
    if (t == 1023) g_bsum[blockIdx.x] = wsum[31];
}

__global__ void k_scanB(int nb) {
    __shared__ int sh[4];
    int t = threadIdx.x, lane = t & 31, wp = t >> 5;
    int v = (t < nb) ? g_bsum[t] : 0;
    int x = v;
    #pragma unroll
    for (int o = 1; o < 32; o <<= 1) {
        int y = __shfl_up_sync(0xffffffffu, x, o);
        if (lane >= o) x += y;
    }
    if (lane == 31) sh[wp] = x;
    __syncthreads();
    int add = 0;
    for (int w = 0; w < wp; ++w) add += sh[w];
    if (t < 128) g_boff[t] = add + x - v;
}

__global__ void k_scanC() {
    int i = blockIdx.x * blockDim.x + threadIdx.x;
    if (i < NN) {
        int r = g_rowoff[i] + g_boff[i >> 10];
        g_rowoff[i] = r;
        g_cursor[i] = r;
    }
    if (i == 0) g_rowoff[NN] = NE;
}

__global__ void k_scatter(const int* __restrict__ src, const int* __restrict__ dst) {
    int e = blockIdx.x * blockDim.x + threadIdx.x;
    if (e < NE) {
        int p = atomicAdd(&g_cursor[dst[e]], 1);
        g_csr[p] = src[e];
    }
}

// ======================= input conversion =======================
// writes: prescaled fp32 plane (x*dinv) + unscaled bf16 hi/lo planes
__global__ void k_featsplit(const float* __restrict__ f) {
    size_t i = ((size_t)blockIdx.x * blockDim.x + threadIdx.x) * 4;
    if (i >= (size_t)NN * FH) return;
    int row = (int)(i >> 7);
    float dv = g_dinv[row];
    float4 v = *(const float4*)(f + i);
    uint2 h, l;
    h.x = pack_hi2(v.x, v.y); h.y = pack_hi2(v.z, v.w);
    l.x = pack_lo2(v.x, v.y); l.y = pack_lo2(v.z, v.w);
    *(uint2*)(&g_X0h[0][i]) = h;
    *(uint2*)(&g_X0l[0][i]) = l;
    float4 p = make_float4(v.x * dv, v.y * dv, v.z * dv, v.w * dv);
    *(float4*)(&g_Hpre[0][i]) = p;
}

__global__ void k_prep_w(const float* __restrict__ W0, const float* __restrict__ Wh) {
    int i = blockIdx.x * blockDim.x + threadIdx.x;
    if (i >= 6 * 384 * 128) return;
    int l = i / (384 * 128);
    int r = i % (384 * 128);
    int k = r / 128, n = r % 128;
    const float* W = (l == 0) ? W0 : (Wh + (size_t)(l - 1) * 384 * 128);
    float v = W[(size_t)k * 128 + n];
    __nv_bfloat16 h = __float2bfloat16(v);
    float lo = v - __bfloat162float(h);
    size_t o = (size_t)l * 128 * 384 + (size_t)n * 384 + k;
    g_Wth[o] = h;
    g_Wtl[o] = __float2bfloat16(lo);
}

// ======================= SpMM: warp-per-node CSR gather (prescaled) =======================
// Ypre rows are already scaled by dinv[s], so the inner loop is a pure gather-add.
// MODE 1: o = -dinv[v] * sum Ypre[s]
// MODE 2: o = -2*dinv[v]*sum Ypre[s] - X0pre[v]*rdinv[v]
template <int MODE, bool WPRE, bool WF32, bool WBF>
__global__ void __launch_bounds__(256) k_spmm(const float* __restrict__ Ypre,
                                              const float* __restrict__ X0pre,
                                              float* __restrict__ outpre,
                                              float* __restrict__ outf,
                                              __nv_bfloat16* __restrict__ oh,
                                              __nv_bfloat16* __restrict__ ol) {
    int w = (blockIdx.x * blockDim.x + threadIdx.x) >> 5;
    int lane = threadIdx.x & 31;
    if (w >= NN) return;
    int beg = g_rowoff[w];
    int end = g_rowoff[w + 1];
    float ax = 0.f, ay = 0.f, az = 0.f, aw = 0.f;
    int i = beg;
    const size_t lo4 = (size_t)(lane * 4);
    for (; i + 4 <= end; i += 4) {
        int s0 = g_csr[i], s1 = g_csr[i + 1], s2 = g_csr[i + 2], s3 = g_csr[i + 3];
        float4 y0 = *(const float4*)(Ypre + (size_t)s0 * FH + lo4);
        float4 y1 = *(const float4*)(Ypre + (size_t)s1 * FH + lo4);
        float4 y2 = *(const float4*)(Ypre + (size_t)s2 * FH + lo4);
        float4 y3 = *(const float4*)(Ypre + (size_t)s3 * FH + lo4);
        ax += (y0.x + y1.x) + (y2.x + y3.x);
        ay += (y0.y + y1.y) + (y2.y + y3.y);
        az += (y0.z + y1.z) + (y2.z + y3.z);
        aw += (y0.w + y1.w) + (y2.w + y3.w);
    }
    for (; i < end; ++i) {
        int s = g_csr[i];
        float4 y = *(const float4*)(Ypre + (size_t)s * FH + lo4);
        ax += y.x; ay += y.y; az += y.z; aw += y.w;
    }
    float dv = g_dinv[w];
    float4 o;
    if (MODE == 1) {
        o.x = -dv * ax; o.y = -dv * ay; o.z = -dv * az; o.w = -dv * aw;
    } else {
        float rd = g_rdinv[w];
        float4 x0 = *(const float4*)(X0pre + (size_t)w * FH + lo4);
        float m = -2.f * dv;
        o.x = fmaf(m, ax, -x0.x * rd);
        o.y = fmaf(m, ay, -x0.y * rd);
        o.z = fmaf(m, az, -x0.z * rd);
        o.w = fmaf(m, aw, -x0.w * rd);
    }
    size_t base = (size_t)w * FH + lo4;
    if (WPRE) {
        float4 p = make_float4(o.x * dv, o.y * dv, o.z * dv, o.w * dv);
        *(float4*)(outpre + base) = p;
    }
    if (WF32) *(float4*)(outf + base) = o;
    if (WBF) {
        uint2 h, l;
        h.x = pack_hi2(o.x, o.y); h.y = pack_hi2(o.z, o.w);
        l.x = pack_lo2(o.x, o.y); l.y = pack_lo2(o.z, o.w);
        *(uint2*)(oh + base) = h;
        *(uint2*)(ol + base) = l;
    }
}

// ======================= mma.sync bf16-pair GEMM =======================
// C[128-tile, 128] = relu( [X0|X1|X2](fp32 as hi+lo bf16) @ W + b )
// 512 threads, 4x4 warp grid, 32x32 warp tiles, K-chunks of 64, 3 passes (hh+hl+lh).
// Epilogue writes prescaled fp32 plane (v*dinv) + unscaled bf16 hi/lo planes.
#define GM_OFF_A_HI 0
#define GM_OFF_A_LO 16384
#define GM_OFF_B_HI 32768
#define GM_OFF_B_LO 49152
#define GM_SMEM_SZ  (65536 + 1024)

__global__ void __launch_bounds__(512) k_gemm_mma(
    const __nv_bfloat16* __restrict__ x0h, const __nv_bfloat16* __restrict__ x0l,
    const float* __restrict__ bias,
    const __nv_bfloat16* __restrict__ wth, const __nv_bfloat16* __restrict__ wtl,
    float* __restrict__ outpre,
    __nv_bfloat16* __restrict__ outh, __nv_bfloat16* __restrict__ outl) {
    extern __shared__ char smem_raw[];
    __shared__ float s_bias[128];
    uint32_t sb0 = smem_u32(smem_raw);
    uint32_t sb = (sb0 + 1023u) & ~1023u;          // 1024B-align for SW128
    char* smem = smem_raw + (sb - sb0);

    const int tid = threadIdx.x, lane = tid & 31, wid = tid >> 5;
    const int wm = wid >> 2, wn = wid & 3;         // 4x4 warp grid
    const int rowBase = blockIdx.x * 128;
    if (tid < 128) s_bias[tid] = bias[tid];

    const __nv_bfloat16* Ah[3] = {x0h, g_B1h, g_B2h};
    const __nv_bfloat16* Al[3] = {x0l, g_B1l, g_B2l};

    float acc[2][4][4];
    #pragma unroll
    for (int a = 0; a < 2; ++a)
        #pragma unroll
        for (int b = 0; b < 4; ++b)
            #pragma unroll
            for (int c = 0; c < 4; ++c) acc[a][b][c] = 0.f;

    const int lrow = lane & 7, seg = lane >> 3;

    #pragma unroll 1
    for (int kc = 0; kc < 6; ++kc) {
        const __nv_bfloat16* __restrict__ ah = Ah[kc >> 1];
        const __nv_bfloat16* __restrict__ al = Al[kc >> 1];
        const int coff = (kc & 1) * 64;
        // ---- load A tiles: 128 rows x 64 bf16 (128B rows, SW128) ----
        #pragma unroll
        for (int t = 0; t < 2; ++t) {
            int idx = tid + t * 512;
            int r = idx >> 3, j = idx & 7;
            int row = rowBase + r;
            uint32_t sw = SWZ((uint32_t)(r * 128 + j * 16));
            uint4 vh = make_uint4(0, 0, 0, 0), vl = make_uint4(0, 0, 0, 0);
            if (row < NN) {
                vh = *((const uint4*)(ah + (size_t)row * FH + coff) + j);
                vl = *((const uint4*)(al + (size_t)row * FH + coff) + j);
            }
            *(uint4*)(smem + GM_OFF_A_HI + sw) = vh;
            *(uint4*)(smem + GM_OFF_A_LO + sw) = vl;
        }
        // ---- load B tiles: 128 n-rows x 64 bf16 from W^T ----
        #pragma unroll
        for (int t = 0; t < 2; ++t) {
            int idx = tid + t * 512;
            int n = idx >> 3, j = idx & 7;
            uint32_t sw = SWZ((uint32_t)(n * 128 + j * 16));
            *(uint4*)(smem + GM_OFF_B_HI + sw) = *((const uint4*)(wth + (size_t)n * 384 + kc * 64) + j);
            *(uint4*)(smem + GM_OFF_B_LO + sw) = *((const uint4*)(wtl + (size_t)n * 384 + kc * 64) + j);
        }
        __syncthreads();

        // ---- compute: 4 k16 steps ----
        #pragma unroll
        for (int kt = 0; kt < 4; ++kt) {
            uint32_t Ahf[2][4], Alf[2][4], Bhf[2][4], Blf[2][4];
            #pragma unroll
            for (int mt = 0; mt < 2; ++mt) {
                int m = wm * 32 + mt * 16 + (seg & 1) * 8 + lrow;
                int kb = kt * 32 + (seg >> 1) * 16;
                uint32_t sw = SWZ((uint32_t)(m * 128 + kb));
                ldmx4(Ahf[mt], sb + GM_OFF_A_HI + sw);
                ldmx4(Alf[mt], sb + GM_OFF_A_LO + sw);
            }
            #pragma unroll
            for (int ntp = 0; ntp < 2; ++ntp) {
                int n = wn * 32 + ntp * 16 + (seg >> 1) * 8 + lrow;
                int kb = kt * 32 + (seg & 1) * 16;
                uint32_t sw = SWZ((uint32_t)(n * 128 + kb));
                ldmx4(Bhf[ntp], sb + GM_OFF_B_HI + sw);
                ldmx4(Blf[ntp], sb + GM_OFF_B_LO + sw);
            }
            #pragma unroll
            for (int mt = 0; mt < 2; ++mt)
                #pragma unroll
                for (int ntp = 0; ntp < 2; ++ntp)
                    #pragma unroll
                    for (int sub = 0; sub < 2; ++sub) {
                        int nj = ntp * 2 + sub;
                        mma_bf16(acc[mt][nj], Ahf[mt], &Bhf[ntp][sub * 2]);
                        mma_bf16(acc[mt][nj], Ahf[mt], &Blf[ntp][sub * 2]);
                        mma_bf16(acc[mt][nj], Alf[mt], &Bhf[ntp][sub * 2]);
                    }
        }
        __syncthreads();
    }

    // ---- epilogue: bias + relu; write prescaled fp32 + bf16 hi/lo ----
    float dvr[2][2];
    #pragma unroll
    for (int mt = 0; mt < 2; ++mt)
        #pragma unroll
        for (int rp = 0; rp < 2; ++rp) {
            int row = rowBase + wm * 32 + mt * 16 + (lane >> 2) + rp * 8;
            dvr[mt][rp] = (row < NN) ? g_dinv[row] : 0.f;
        }
    #pragma unroll
    for (int mt = 0; mt < 2; ++mt) {
        #pragma unroll
        for (int nj = 0; nj < 4; ++nj) {
            int col = wn * 32 + nj * 8 + (lane & 3) * 2;
            float bz0 = s_bias[col], bz1 = s_bias[col + 1];
            #pragma unroll
            for (int rp = 0; rp < 2; ++rp) {
                int row = rowBase + wm * 32 + mt * 16 + (lane >> 2) + rp * 8;
                if (row < NN) {
                    float v0 = fmaxf(acc[mt][nj][rp * 2 + 0] + bz0, 0.f);
                    float v1 = fmaxf(acc[mt][nj][rp * 2 + 1] + bz1, 0.f);
                    float dv = dvr[mt][rp];
                    size_t base = (size_t)row * FH + col;
                    *(float2*)(outpre + base) = make_float2(v0 * dv, v1 * dv);
                    *(uint32_t*)(outh + base) = pack_hi2(v0, v1);
                    *(uint32_t*)(outl + base) = pack_lo2(v0, v1);
                }
            }
        }
    }
}

// ======================= SIMT GEMM for final layer (CO=40) =======================
// X0 input is the prescaled plane; un-scale rows by rdinv on load (UNS0 = true).
template <int CO, int TM, int TN>
__global__ void k_gemm_simt(const float* __restrict__ X0, const float* __restrict__ X1,
                            const float* __restrict__ X2, const float* __restrict__ W,
                            const float* __restrict__ bias, float* __restrict__ out) {
    constexpr int BM = 128, BK = 16;
    constexpr int NTX = CO / TN;
    constexpr int NTY = BM / TM;
    constexpr int NT = NTX * NTY;
    __shared__ float As[BK][BM + 1];
    __shared__ float Bs[BK][CO];
    const int tid = threadIdx.x;
    const int tx = tid % NTX;
    const int ty = tid / NTX;
    const int rowBase = blockIdx.x * BM;

    float acc[TM][TN];
    #pragma unroll
    for (int m = 0; m < TM; ++m)
        #pragma unroll
        for (int n = 0; n < TN; ++n) acc[m][n] = 0.f;

    #pragma unroll 1
    for (int kt = 0; kt < 24; ++kt) {
        const float* __restrict__ A = (kt < 8) ? X0 : ((kt < 16) ? X1 : X2);
        const bool unscale = (kt < 8);
        const int kcol = (kt & 7) * BK;
        for (int i = tid; i < BM * BK; i += NT) {
            int r = i >> 4, k = i & 15;
            int row = rowBase + r;
            float v = 0.f;
            if (row < NN) {
                v = A[(size_t)row * FH + kcol + k];
                if (unscale) v *= g_rdinv[row];
            }
            As[k][r] = v;
        }
        for (int i = tid; i < BK * CO; i += NT) {
            int k = i / CO, c = i % CO;
            Bs[k][c] = W[(size_t)(kt * BK + k) * CO + c];
        }
        __syncthreads();
        #pragma unroll
        for (int k = 0; k < BK; ++k) {
            float ra[TM], rb[TN];
            #pragma unroll
            for (int m = 0; m < TM; ++m) ra[m] = As[k][ty * TM + m];
            #pragma unroll
            for (int n = 0; n < TN; ++n) rb[n] = Bs[k][tx * TN + n];
            #pragma unroll
            for (int m = 0; m < TM; ++m)
                #pragma unroll
                for (int n = 0; n < TN; ++n)
                    acc[m][n] = fmaf(ra[m], rb[n], acc[m][n]);
        }
        __syncthreads();
    }
    #pragma unroll
    for (int m = 0; m < TM; ++m) {
        int row = rowBase + ty * TM + m;
        if (row < NN) {
            #pragma unroll
            for (int n = 0; n < TN; ++n) {
                int c = tx * TN + n;
                out[(size_t)row * CO + c] = fmaxf(acc[m][n] + bias[c], 0.f);
            }
        }
    }
}

// ======================= host launcher =======================
extern "C" void kernel_launch(void* const* d_in, const int* in_sizes, int n_in,
                              void* d_out, int out_size) {
    const float* feat = (const float*)d_in[0];
    const int*   src  = (const int*)d_in[1];
    const int*   dst  = (const int*)d_in[2];
    const float* W0   = (const float*)d_in[3];
    const float* b0   = (const float*)d_in[4];
    const float* Wh   = (const float*)d_in[5];
    const float* bh   = (const float*)d_in[6];
    const float* Wl   = (const float*)d_in[7];
    const float* bl   = (const float*)d_in[8];
    float* out = (float*)d_out;

    float *Hpre, *B1pre, *B1f, *B2f;
    __nv_bfloat16 *X0h, *X0l, *B1h, *B1l, *B2h, *B2l, *Wth, *Wtl;
    cudaGetSymbolAddress((void**)&Hpre,  g_Hpre);
    cudaGetSymbolAddress((void**)&B1pre, g_B1pre);
    cudaGetSymbolAddress((void**)&B1f,   g_B1f);
    cudaGetSymbolAddress((void**)&B2f,   g_B2f);
    cudaGetSymbolAddress((void**)&X0h,   g_X0h);
    cudaGetSymbolAddress((void**)&X0l,   g_X0l);
    cudaGetSymbolAddress((void**)&B1h,   g_B1h);
    cudaGetSymbolAddress((void**)&B1l,   g_B1l);
    cudaGetSymbolAddress((void**)&B2h,   g_B2h);
    cudaGetSymbolAddress((void**)&B2l,   g_B2l);
    cudaGetSymbolAddress((void**)&Wth,   g_Wth);
    cudaGetSymbolAddress((void**)&Wtl,   g_Wtl);

    cudaFuncSetAttribute(k_gemm_mma, cudaFuncAttributeMaxDynamicSharedMemorySize, GM_SMEM_SZ);

    const int TPB = 256;
    const int nodeBlocks = (NN + TPB - 1) / TPB;
    const int edgeBlocks = (NE + TPB - 1) / TPB;
    const int scanBlocks = (NN + 1023) / 1024;   // 98

    // preprocessing
    k_zero_deg<<<nodeBlocks, TPB>>>();
    k_hist<<<edgeBlocks, TPB>>>(dst);
    k_dinv<<<nodeBlocks, TPB>>>();
    k_scanA<<<scanBlocks, 1024>>>();
    k_scanB<<<1, 128>>>(scanBlocks);
    k_scanC<<<nodeBlocks, TPB>>>();
    k_scatter<<<edgeBlocks, TPB>>>(src, dst);

    // input conversion (needs dinv)
    k_featsplit<<<(NN * FH / 4 + TPB - 1) / TPB, TPB>>>(feat);
    k_prep_w<<<(6 * 384 * 128 + TPB - 1) / TPB, TPB>>>(W0, Wh);

    const size_t SL = (size_t)NN * FH;
    const int spmmBlocks = (NN * 32 + TPB - 1) / TPB;
    const int tileBlocks = (NN + 127) / 128;

    int cur = 0;
    for (int l = 0; l < 6; ++l) {
        const float* curpre = Hpre + (size_t)cur * SL;
        // X1 = -spmm(X0): write prescaled plane (for spmm2) + unscaled bf16 planes
        k_spmm<1, true, false, true><<<spmmBlocks, TPB>>>(curpre, nullptr, B1pre, nullptr, B1h, B1l);
        // X2 = -2*spmm(X1) - X0: bf16 planes only
        k_spmm<2, false, false, true><<<spmmBlocks, TPB>>>(B1pre, curpre, nullptr, nullptr, B2h, B2l);
        const float* bias = (l == 0) ? b0 : (bh + (size_t)(l - 1) * 128);
        int nxt = 1 - cur;
        k_gemm_mma<<<tileBlocks, 512, GM_SMEM_SZ>>>(
            X0h + (size_t)cur * SL, X0l + (size_t)cur * SL,
            bias, Wth + (size_t)l * 128 * 384, Wtl + (size_t)l * 128 * 384,
            Hpre + (size_t)nxt * SL,
            X0h + (size_t)nxt * SL, X0l + (size_t)nxt * SL);
        cur = nxt;
    }
    // final layer: fp32 SIMT (CO=40)
    const float* curpre = Hpre + (size_t)cur * SL;
    k_spmm<1, true, true, false><<<spmmBlocks, TPB>>>(curpre, nullptr, B1pre, B1f, nullptr, nullptr);
    k_spmm<2, false, true, false><<<spmmBlocks, TPB>>>(B1pre, curpre, nullptr, B2f, nullptr, nullptr);
    k_gemm_simt<FO, 8, 5><<<tileBlocks, 128>>>(curpre, B1f, B2f, Wl, bl, out);
}

// round 5
// speedup vs baseline: 1.7001x; 1.0603x over previous
#include <cuda_runtime.h>
#include <cuda_bf16.h>
#include <cstdint>

#define NN 100000
#define NE 1600000
#define FH 128
#define FO 40

// ======================= device scratch (no allocs allowed) =======================
__device__ int   g_deg[NN];
__device__ float g_dinv[NN];
__device__ float g_rdinv[NN];
__device__ int   g_rowoff[NN + 1];
__device__ int   g_cursor[NN];
__device__ int   g_csr[NE];
__device__ int   g_bsum[128];
__device__ int   g_boff[128];

// prescaled (v*dinv) bf16 hi/lo activation planes
__device__ __nv_bfloat16 g_Ph[2][(size_t)NN * FH];   // layer I/O ping-pong, hi
__device__ __nv_bfloat16 g_Pl[2][(size_t)NN * FH];   // lo
__device__ __nv_bfloat16 g_Q1h[(size_t)NN * FH];     // X1 prescaled hi
__device__ __nv_bfloat16 g_Q1l[(size_t)NN * FH];
__device__ __nv_bfloat16 g_Q2h[(size_t)NN * FH];     // X2 prescaled hi
__device__ __nv_bfloat16 g_Q2l[(size_t)NN * FH];
__device__ float g_B1f[(size_t)NN * FH];             // X1 unscaled fp32 (final layer)
__device__ float g_B2f[(size_t)NN * FH];             // X2 unscaled fp32 (final layer)
__device__ __nv_bfloat16 g_Wth[6 * 128 * 384];       // W^T per layer: [n=128][k=384], hi
__device__ __nv_bfloat16 g_Wtl[6 * 128 * 384];       // lo

// ======================= helpers =======================
__device__ __forceinline__ uint32_t smem_u32(const void* p) {
    uint32_t a;
    asm("{ .reg .u64 t; cvta.to.shared.u64 t, %1; cvt.u32.u64 %0, t; }" : "=r"(a) : "l"(p));
    return a;
}

#define SWZ(off) ((off) ^ (((off) >> 3) & 0x70))

__device__ __forceinline__ void ldmx4(uint32_t* r, uint32_t addr) {
    asm volatile("ldmatrix.sync.aligned.m8n8.x4.shared.b16 {%0,%1,%2,%3}, [%4];"
                 : "=r"(r[0]), "=r"(r[1]), "=r"(r[2]), "=r"(r[3]) : "r"(addr));
}

__device__ __forceinline__ void mma_bf16(float* d, const uint32_t* a, const uint32_t* b) {
    asm volatile(
        "mma.sync.aligned.m16n8k16.row.col.f32.bf16.bf16.f32 "
        "{%0,%1,%2,%3}, {%4,%5,%6,%7}, {%8,%9}, {%0,%1,%2,%3};"
        : "+f"(d[0]), "+f"(d[1]), "+f"(d[2]), "+f"(d[3])
        : "r"(a[0]), "r"(a[1]), "r"(a[2]), "r"(a[3]), "r"(b[0]), "r"(b[1]));
}

__device__ __forceinline__ void cpa16(uint32_t saddr, const void* g, bool pred) {
    asm volatile("cp.async.cg.shared.global [%0], [%1], 16, %2;"
                 :: "r"(saddr), "l"(g), "r"(pred ? 16 : 0) : "memory");
}
#define CP_COMMIT() asm volatile("cp.async.commit_group;" ::: "memory")
#define CP_WAIT(n)  asm volatile("cp.async.wait_group %0;" :: "n"(n) : "memory")

__device__ __forceinline__ float blo(uint32_t u) { return __uint_as_float(u << 16); }
__device__ __forceinline__ float bhi(uint32_t u) { return __uint_as_float(u & 0xffff0000u); }

__device__ __forceinline__ uint32_t pack_hi2(float a, float b) {
    __nv_bfloat16 ha = __float2bfloat16(a), hb = __float2bfloat16(b);
    return (uint32_t)__bfloat16_as_ushort(ha) | ((uint32_t)__bfloat16_as_ushort(hb) << 16);
}
__device__ __forceinline__ uint32_t pack_lo2(float a, float b) {
    __nv_bfloat16 ha = __float2bfloat16(a), hb = __float2bfloat16(b);
    __nv_bfloat16 la = __float2bfloat16(a - __bfloat162float(ha));
    __nv_bfloat16 lb = __float2bfloat16(b - __bfloat162float(hb));
    return (uint32_t)__bfloat16_as_ushort(la) | ((uint32_t)__bfloat16_as_ushort(lb) << 16);
}

// ======================= graph preprocessing =======================
__global__ void k_zero_deg() {
    int i = blockIdx.x * blockDim.x + threadIdx.x;
    if (i < NN) g_deg[i] = 0;
}
__global__ void k_hist(const int* __restrict__ dst) {
    int e = blockIdx.x * blockDim.x + threadIdx.x;
    if (e < NE) atomicAdd(&g_deg[dst[e]], 1);
}
__global__ void k_dinv() {
    int i = blockIdx.x * blockDim.x + threadIdx.x;
    if (i < NN) {
        int d = g_deg[i];
        float df = (float)(d > 1 ? d : 1);
        g_dinv[i] = rsqrtf(df);
        g_rdinv[i] = sqrtf(df);
    }
}

__global__ void __launch_bounds__(1024) k_scanA() {
    __shared__ int wsum[32];
    int t = threadIdx.x, lane = t & 31, wp = t >> 5;
    int i = blockIdx.x * 1024 + t;
    int v = (i < NN) ? g_deg[i] : 0;
    int x = v;
    #pragma unroll
    for (int o = 1; o < 32; o <<= 1) {
        int y = __shfl_up_sync(0xffffffffu, x, o);
        if (lane >= o) x += y;
    }
    if (lane == 31) wsum[wp] = x;
    __syncthreads();
    if (wp == 0) {
        int s = wsum[lane];
        #pragma unroll
        for (int o = 1; o < 32; o <<= 1) {
            int y = __shfl_up_sync(0xffffffffu, s, o);
            if (lane >= o) s += y;
        }
        wsum[lane] = s;
    }
    __syncthreads();
    int off = (wp ? wsum[wp - 1] : 0);
    if (i < NN) g_rowoff[i] = off + x - v;
    if (t == 1023) g_bsum[blockIdx.x] = wsum[31];
}

__global__ void k_scanB(int nb) {
    __shared__ int sh[4];
    int t = threadIdx.x, lane = t & 31, wp = t >> 5;
    int v = (t < nb) ? g_bsum[t] : 0;
    int x = v;
    #pragma unroll
    for (int o = 1; o < 32; o <<= 1) {
        int y = __shfl_up_sync(0xffffffffu, x, o);
        if (lane >= o) x += y;
    }
    if (lane == 31) sh[wp] = x;
    __syncthreads();
    int add = 0;
    for (int w = 0; w < wp; ++w) add += sh[w];
    if (t < 128) g_boff[t] = add + x - v;
}

__global__ void k_scanC() {
    int i = blockIdx.x * blockDim.x + threadIdx.x;
    if (i < NN) {
        int r = g_rowoff[i] + g_boff[i >> 10];
        g_rowoff[i] = r;
        g_cursor[i] = r;
    }
    if (i == 0) g_rowoff[NN] = NE;
}

__global__ void k_scatter(const int* __restrict__ src, const int* __restrict__ dst) {
    int e = blockIdx.x * blockDim.x + threadIdx.x;
    if (e < NE) {
        int p = atomicAdd(&g_cursor[dst[e]], 1);
        g_csr[p] = src[e];
    }
}

// ======================= input conversion =======================
// writes prescaled hi/lo planes of (feat * dinv)
__global__ void k_featsplit(const float* __restrict__ f) {
    size_t i = ((size_t)blockIdx.x * blockDim.x + threadIdx.x) * 4;
    if (i >= (size_t)NN * FH) return;
    int row = (int)(i >> 7);
    float dv = g_dinv[row];
    float4 v = *(const float4*)(f + i);
    v.x *= dv; v.y *= dv; v.z *= dv; v.w *= dv;
    uint2 h, l;
    h.x = pack_hi2(v.x, v.y); h.y = pack_hi2(v.z, v.w);
    l.x = pack_lo2(v.x, v.y); l.y = pack_lo2(v.z, v.w);
    *(uint2*)(&g_Ph[0][i]) = h;
    *(uint2*)(&g_Pl[0][i]) = l;
}

__global__ void k_prep_w(const float* __restrict__ W0, const float* __restrict__ Wh) {
    int i = blockIdx.x * blockDim.x + threadIdx.x;
    if (i >= 6 * 384 * 128) return;
    int l = i / (384 * 128);
    int r = i % (384 * 128);
    int k = r / 128, n = r % 128;
    const float* W = (l == 0) ? W0 : (Wh + (size_t)(l - 1) * 384 * 128);
    float v = W[(size_t)k * 128 + n];
    __nv_bfloat16 h = __float2bfloat16(v);
    float lo = v - __bfloat162float(h);
    size_t o = (size_t)l * 128 * 384 + (size_t)n * 384 + k;
    g_Wth[o] = h;
    g_Wtl[o] = __float2bfloat16(lo);
}

// ======================= SpMM: warp-per-node CSR gather over hi/lo planes ========
// All planes are prescaled: stored = value * dinv[row].
// MODE 1: X1p = -dv^2 * sum Yp[s]
// MODE 2: X2p = -2*dv^2 * sum Yp[s] - X0p[w]
// WHL: write hi/lo planes of result (prescaled). WF32: write unscaled fp32 (result*rdinv).
template <int MODE, bool WHL, bool WF32>
__global__ void __launch_bounds__(256) k_spmm(
    const __nv_bfloat16* __restrict__ Yh, const __nv_bfloat16* __restrict__ Yl,
    const __nv_bfloat16* __restrict__ X0h_, const __nv_bfloat16* __restrict__ X0l_,
    __nv_bfloat16* __restrict__ oh, __nv_bfloat16* __restrict__ ol,
    float* __restrict__ outf) {
    int w = (blockIdx.x * blockDim.x + threadIdx.x) >> 5;
    int lane = threadIdx.x & 31;
    if (w >= NN) return;
    int beg = g_rowoff[w];
    int end = g_rowoff[w + 1];
    const size_t lo4 = (size_t)(lane * 4);
    float ah0 = 0.f, ah1 = 0.f, ah2 = 0.f, ah3 = 0.f;
    float al0 = 0.f, al1 = 0.f, al2 = 0.f, al3 = 0.f;
    int i = beg;
    for (; i + 2 <= end; i += 2) {
        int s0 = g_csr[i], s1 = g_csr[i + 1];
        uint2 h0 = *(const uint2*)(Yh + (size_t)s0 * FH + lo4);
        uint2 l0 = *(const uint2*)(Yl + (size_t)s0 * FH + lo4);
        uint2 h1 = *(const uint2*)(Yh + (size_t)s1 * FH + lo4);
        uint2 l1 = *(const uint2*)(Yl + (size_t)s1 * FH + lo4);
        ah0 += blo(h0.x) + blo(h1.x);  al0 += blo(l0.x) + blo(l1.x);
        ah1 += bhi(h0.x) + bhi(h1.x);  al1 += bhi(l0.x) + bhi(l1.x);
        ah2 += blo(h0.y) + blo(h1.y);  al2 += blo(l0.y) + blo(l1.y);
        ah3 += bhi(h0.y) + bhi(h1.y);  al3 += bhi(l0.y) + bhi(l1.y);
    }
    if (i < end) {
        int s = g_csr[i];
        uint2 h0 = *(const uint2*)(Yh + (size_t)s * FH + lo4);
        uint2 l0 = *(const uint2*)(Yl + (size_t)s * FH + lo4);
        ah0 += blo(h0.x);  al0 += blo(l0.x);
        ah1 += bhi(h0.x);  al1 += bhi(l0.x);
        ah2 += blo(h0.y);  al2 += blo(l0.y);
        ah3 += bhi(h0.y);  al3 += bhi(l0.y);
    }
    float s0 = ah0 + al0, s1 = ah1 + al1, s2 = ah2 + al2, s3 = ah3 + al3;
    float dv = g_dinv[w];
    float dv2 = dv * dv;
    float4 p;
    if (MODE == 1) {
        float m = -dv2;
        p = make_float4(m * s0, m * s1, m * s2, m * s3);
    } else {
        uint2 xh = *(const uint2*)(X0h_ + (size_t)w * FH + lo4);
        uint2 xl = *(const uint2*)(X0l_ + (size_t)w * FH + lo4);
        float m = -2.f * dv2;
        p.x = fmaf(m, s0, -(blo(xh.x) + blo(xl.x)));
        p.y = fmaf(m, s1, -(bhi(xh.x) + bhi(xl.x)));
        p.z = fmaf(m, s2, -(blo(xh.y) + blo(xl.y)));
        p.w = fmaf(m, s3, -(bhi(xh.y) + bhi(xl.y)));
    }
    size_t base = (size_t)w * FH + lo4;
    if (WHL) {
        uint2 h, l;
        h.x = pack_hi2(p.x, p.y); h.y = pack_hi2(p.z, p.w);
        l.x = pack_lo2(p.x, p.y); l.y = pack_lo2(p.z, p.w);
        *(uint2*)(oh + base) = h;
        *(uint2*)(ol + base) = l;
    }
    if (WF32) {
        float rd = g_rdinv[w];
        *(float4*)(outf + base) = make_float4(p.x * rd, p.y * rd, p.z * rd, p.w * rd);
    }
}

// ======================= cp.async pipelined mma.sync bf16-pair GEMM ==============
// C = relu( rdinv[m] * ([X0p|X1p|X2p] @ W) + b ); store (C*dinv[m]) hi/lo planes.
// 512 threads, 4x4 warp grid, 32x32 warp tiles, 6 K-chunks of 64, 2-stage pipeline.
#define GM_A_HI 0
#define GM_A_LO 16384
#define GM_B_HI 32768
#define GM_B_LO 49152
#define GM_ST   65536
#define GM_SMEM_SZ (2 * GM_ST)

__device__ __forceinline__ void gm_load_chunk(
    uint32_t base, int kc, int rowBase, int tid,
    const __nv_bfloat16* __restrict__ ah, const __nv_bfloat16* __restrict__ al,
    const __nv_bfloat16* __restrict__ wth, const __nv_bfloat16* __restrict__ wtl) {
    const int coff = (kc & 1) * 64;
    #pragma unroll
    for (int t = 0; t < 2; ++t) {
        int idx = tid + t * 512;
        int r = idx >> 3, j = idx & 7;
        int row = rowBase + r;
        bool ok = row < NN;
        int rowc = ok ? row : (NN - 1);
        uint32_t sw = SWZ((uint32_t)(r * 128 + j * 16));
        cpa16(base + GM_A_HI + sw, ah + (size_t)rowc * FH + coff + j * 8, ok);
        cpa16(base + GM_A_LO + sw, al + (size_t)rowc * FH + coff + j * 8, ok);
    }
    #pragma unroll
    for (int t = 0; t < 2; ++t) {
        int idx = tid + t * 512;
        int n = idx >> 3, j = idx & 7;
        uint32_t sw = SWZ((uint32_t)(n * 128 + j * 16));
        cpa16(base + GM_B_HI + sw, wth + (size_t)n * 384 + kc * 64 + j * 8, true);
        cpa16(base + GM_B_LO + sw, wtl + (size_t)n * 384 + kc * 64 + j * 8, true);
    }
}

__global__ void __launch_bounds__(512) k_gemm_mma(
    const __nv_bfloat16* __restrict__ x0h, const __nv_bfloat16* __restrict__ x0l,
    const float* __restrict__ bias,
    const __nv_bfloat16* __restrict__ wth, const __nv_bfloat16* __restrict__ wtl,
    __nv_bfloat16* __restrict__ outh, __nv_bfloat16* __restrict__ outl) {
    extern __shared__ char smem_raw[];
    __shared__ float s_bias[128];
    uint32_t sb0 = smem_u32(smem_raw);
    uint32_t sb = (sb0 + 1023u) & ~1023u;          // 1024B-align for SW128

    const int tid = threadIdx.x, lane = tid & 31, wid = tid >> 5;
    const int wm = wid >> 2, wn = wid & 3;         // 4x4 warp grid
    const int rowBase = blockIdx.x * 128;
    if (tid < 128) s_bias[tid] = bias[tid];

    const __nv_bfloat16* Ah[3] = {x0h, g_Q1h, g_Q2h};
    const __nv_bfloat16* Al[3] = {x0l, g_Q1l, g_Q2l};

    float acc[2][4][4];
    #pragma unroll
    for (int a = 0; a < 2; ++a)
        #pragma unroll
        for (int b = 0; b < 4; ++b)
            #pragma unroll
            for (int c = 0; c < 4; ++c) acc[a][b][c] = 0.f;

    const int lrow = lane & 7, seg = lane >> 3;

    // prologue: stage 0 <- chunk 0
    gm_load_chunk(sb, 0, rowBase, tid, Ah[0], Al[0], wth, wtl);
    CP_COMMIT();

    #pragma unroll 1
    for (int kc = 0; kc < 6; ++kc) {
        if (kc < 5) {
            int nk = kc + 1;
            gm_load_chunk(sb + ((nk & 1) ? GM_ST : 0), nk, rowBase, tid,
                          Ah[nk >> 1], Al[nk >> 1], wth, wtl);
            CP_COMMIT();
            CP_WAIT(1);
        } else {
            CP_WAIT(0);
        }
        __syncthreads();

        const uint32_t st = sb + ((kc & 1) ? GM_ST : 0);
        #pragma unroll
        for (int kt = 0; kt < 4; ++kt) {
            uint32_t Ahf[2][4], Alf[2][4], Bhf[2][4], Blf[2][4];
            #pragma unroll
            for (int mt = 0; mt < 2; ++mt) {
                int m = wm * 32 + mt * 16 + (seg & 1) * 8 + lrow;
                int kb = kt * 32 + (seg >> 1) * 16;
                uint32_t sw = SWZ((uint32_t)(m * 128 + kb));
                ldmx4(Ahf[mt], st + GM_A_HI + sw);
                ldmx4(Alf[mt], st + GM_A_LO + sw);
            }
            #pragma unroll
            for (int ntp = 0; ntp < 2; ++ntp) {
                int n = wn * 32 + ntp * 16 + (seg >> 1) * 8 + lrow;
                int kb = kt * 32 + (seg & 1) * 16;
                uint32_t sw = SWZ((uint32_t)(n * 128 + kb));
                ldmx4(Bhf[ntp], st + GM_B_HI + sw);
                ldmx4(Blf[ntp], st + GM_B_LO + sw);
            }
            #pragma unroll
            for (int mt = 0; mt < 2; ++mt)
                #pragma unroll
                for (int ntp = 0; ntp < 2; ++ntp)
                    #pragma unroll
                    for (int sub = 0; sub < 2; ++sub) {
                        int nj = ntp * 2 + sub;
                        mma_bf16(acc[mt][nj], Ahf[mt], &Bhf[ntp][sub * 2]);
                        mma_bf16(acc[mt][nj], Ahf[mt], &Blf[ntp][sub * 2]);
                        mma_bf16(acc[mt][nj], Alf[mt], &Bhf[ntp][sub * 2]);
                    }
        }
        __syncthreads();
    }

    // ---- epilogue: v = relu(acc*rdinv + b); store hi/lo of v*dinv ----
    float dvr[2][2], rdr[2][2];
    #pragma unroll
    for (int mt = 0; mt < 2; ++mt)
        #pragma unroll
        for (int rp = 0; rp < 2; ++rp) {
            int row = rowBase + wm * 32 + mt * 16 + (lane >> 2) + rp * 8;
            bool ok = row < NN;
            dvr[mt][rp] = ok ? g_dinv[row] : 0.f;
            rdr[mt][rp] = ok ? g_rdinv[row] : 0.f;
        }
    #pragma unroll
    for (int mt = 0; mt < 2; ++mt) {
        #pragma unroll
        for (int nj = 0; nj < 4; ++nj) {
            int col = wn * 32 + nj * 8 + (lane & 3) * 2;
            float bz0 = s_bias[col], bz1 = s_bias[col + 1];
            #pragma unroll
            for (int rp = 0; rp < 2; ++rp) {
                int row = rowBase + wm * 32 + mt * 16 + (lane >> 2) + rp * 8;
                if (row < NN) {
                    float rd = rdr[mt][rp], dv = dvr[mt][rp];
                    float v0 = fmaxf(fmaf(acc[mt][nj][rp * 2 + 0], rd, bz0), 0.f) * dv;
                    float v1 = fmaxf(fmaf(acc[mt][nj][rp * 2 + 1], rd, bz1), 0.f) * dv;
                    size_t base = (size_t)row * FH + col;
                    *(uint32_t*)(outh + base) = pack_hi2(v0, v1);
                    *(uint32_t*)(outl + base) = pack_lo2(v0, v1);
                }
            }
        }
    }
}

// ======================= SIMT GEMM for final layer (CO=40) =======================
// X0 reconstructed from prescaled hi/lo planes (* rdinv); X1/X2 unscaled fp32.
template <int CO, int TM, int TN>
__global__ void k_gemm_simt(const __nv_bfloat16* __restrict__ X0h_,
                            const __nv_bfloat16* __restrict__ X0l_,
                            const float* __restrict__ X1, const float* __restrict__ X2,
                            const float* __restrict__ W,
                            const float* __restrict__ bias, float* __restrict__ out) {
    constexpr int BM = 128, BK = 16;
    constexpr int NTX = CO / TN;
    constexpr int NTY = BM / TM;
    constexpr int NT = NTX * NTY;
    __shared__ float As[BK][BM + 1];
    __shared__ float Bs[BK][CO];
    const int tid = threadIdx.x;
    const int tx = tid % NTX;
    const int ty = tid / NTX;
    const int rowBase = blockIdx.x * BM;

    float acc[TM][TN];
    #pragma unroll
    for (int m = 0; m < TM; ++m)
        #pragma unroll
        for (int n = 0; n < TN; ++n) acc[m][n] = 0.f;

    #pragma unroll 1
    for (int kt = 0; kt < 24; ++kt) {
        const int kcol = (kt & 7) * BK;
        for (int i = tid; i < BM * BK; i += NT) {
            int r = i >> 4, k = i & 15;
            int row = rowBase + r;
            float v = 0.f;
            if (row < NN) {
                size_t off = (size_t)row * FH + kcol + k;
                if (kt < 8) {
                    uint32_t hu = (uint32_t)__bfloat16_as_ushort(X0h_[off]) << 16;
                    uint32_t lu = (uint32_t)__bfloat16_as_ushort(X0l_[off]) << 16;
                    v = (__uint_as_float(hu) + __uint_as_float(lu)) * g_rdinv[row];
                } else if (kt < 16) {
                    v = X1[off];
                } else {
                    v = X2[off];
                }
            }
            As[k][r] = v;
        }
        for (int i = tid; i < BK * CO; i += NT) {
            int k = i / CO, c = i % CO;
            Bs[k][c] = W[(size_t)(kt * BK + k) * CO + c];
        }
        __syncthreads();
        #pragma unroll
        for (int k = 0; k < BK; ++k) {
            float ra[TM], rb[TN];
            #pragma unroll
            for (int m = 0; m < TM; ++m) ra[m] = As[k][ty * TM + m];
            #pragma unroll
            for (int n = 0; n < TN; ++n) rb[n] = Bs[k][tx * TN + n];
            #pragma unroll
            for (int m = 0; m < TM; ++m)
                #pragma unroll
                for (int n = 0; n < TN; ++n)
                    acc[m][n] = fmaf(ra[m], rb[n], acc[m][n]);
        }
        __syncthreads();
    }
    #pragma unroll
    for (int m = 0; m < TM; ++m) {
        int row = rowBase + ty * TM + m;
        if (row < NN) {
            #pragma unroll
            for (int n = 0; n < TN; ++n) {
                int c = tx * TN + n;
                out[(size_t)row * CO + c] = fmaxf(acc[m][n] + bias[c], 0.f);
            }
        }
    }
}

// ======================= host launcher =======================
extern "C" void kernel_launch(void* const* d_in, const int* in_sizes, int n_in,
                              void* d_out, int out_size) {
    const float* feat = (const float*)d_in[0];
    const int*   src  = (const int*)d_in[1];
    const int*   dst  = (const int*)d_in[2];
    const float* W0   = (const float*)d_in[3];
    const float* b0   = (const float*)d_in[4];
    const float* Wh   = (const float*)d_in[5];
    const float* bh   = (const float*)d_in[6];
    const float* Wl   = (const float*)d_in[7];
    const float* bl   = (const float*)d_in[8];
    float* out = (float*)d_out;

    float *B1f, *B2f;
    __nv_bfloat16 *Ph, *Pl, *Q1h, *Q1l, *Q2h, *Q2l, *Wth, *Wtl;
    cudaGetSymbolAddress((void**)&Ph,  g_Ph);
    cudaGetSymbolAddress((void**)&Pl,  g_Pl);
    cudaGetSymbolAddress((void**)&Q1h, g_Q1h);
    cudaGetSymbolAddress((void**)&Q1l, g_Q1l);
    cudaGetSymbolAddress((void**)&Q2h, g_Q2h);
    cudaGetSymbolAddress((void**)&Q2l, g_Q2l);
    cudaGetSymbolAddress((void**)&B1f, g_B1f);
    cudaGetSymbolAddress((void**)&B2f, g_B2f);
    cudaGetSymbolAddress((void**)&Wth, g_Wth);
    cudaGetSymbolAddress((void**)&Wtl, g_Wtl);

    cudaFuncSetAttribute(k_gemm_mma, cudaFuncAttributeMaxDynamicSharedMemorySize,
                         GM_SMEM_SZ + 1024);

    const int TPB = 256;
    const int nodeBlocks = (NN + TPB - 1) / TPB;
    const int edgeBlocks = (NE + TPB - 1) / TPB;
    const int scanBlocks = (NN + 1023) / 1024;   // 98

    // preprocessing
    k_zero_deg<<<nodeBlocks, TPB>>>();
    k_hist<<<edgeBlocks, TPB>>>(dst);
    k_dinv<<<nodeBlocks, TPB>>>();
    k_scanA<<<scanBlocks, 1024>>>();
    k_scanB<<<1, 128>>>(scanBlocks);
    k_scanC<<<nodeBlocks, TPB>>>();
    k_scatter<<<edgeBlocks, TPB>>>(src, dst);

    // input conversion (needs dinv)
    k_featsplit<<<(NN * FH / 4 + TPB - 1) / TPB, TPB>>>(feat);
    k_prep_w<<<(6 * 384 * 128 + TPB - 1) / TPB, TPB>>>(W0, Wh);

    const size_t SL = (size_t)NN * FH;
    const int spmmBlocks = (NN * 32 + TPB - 1) / TPB;
    const int tileBlocks = (NN + 127) / 128;

    int cur = 0;
    for (int l = 0; l < 6; ++l) {
        const __nv_bfloat16* ch = Ph + (size_t)cur * SL;
        const __nv_bfloat16* cl = Pl + (size_t)cur * SL;
        k_spmm<1, true, false><<<spmmBlocks, TPB>>>(ch, cl, nullptr, nullptr, Q1h, Q1l, nullptr);
        k_spmm<2, true, false><<<spmmBlocks, TPB>>>(Q1h, Q1l, ch, cl, Q2h, Q2l, nullptr);
        const float* bias = (l == 0) ? b0 : (bh + (size_t)(l - 1) * 128);
        int nxt = 1 - cur;
        k_gemm_mma<<<tileBlocks, 512, GM_SMEM_SZ + 1024>>>(
            ch, cl, bias,
            Wth + (size_t)l * 128 * 384, Wtl + (size_t)l * 128 * 384,
            Ph + (size_t)nxt * SL, Pl + (size_t)nxt * SL);
        cur = nxt;
    }
    // final layer: fp32 SIMT (CO=40)
    const __nv_bfloat16* ch = Ph + (size_t)cur * SL;
    const __nv_bfloat16* cl = Pl + (size_t)cur * SL;
    k_spmm<1, true, true><<<spmmBlocks, TPB>>>(ch, cl, nullptr, nullptr, Q1h, Q1l, B1f);
    k_spmm<2, false, true><<<spmmBlocks, TPB>>>(Q1h, Q1l, ch, cl, nullptr, nullptr, B2f);
    k_gemm_simt<FO, 8, 5><<<tileBlocks, 128>>>(ch, cl, B1f, B2f, Wl, bl, out);
}

// round 6
// speedup vs baseline: 1.8079x; 1.0634x over previous
#include <cuda_runtime.h>
#include <cuda_bf16.h>
#include <cstdint>

#define NN 100000
#define NE 1600000
#define FH 128
#define FO 40

// ======================= device scratch (no allocs allowed) =======================
__device__ int   g_deg[NN];
__device__ float g_dinv[NN];
__device__ float g_rdinv[NN];
__device__ int   g_rowoff[NN + 1];
__device__ int   g_cursor[NN];
__device__ int   g_csr[NE];
__device__ int   g_bsum[128];
__device__ int   g_boff[128];

// prescaled (v*dinv) bf16 hi/lo activation planes (exact path: GEMM + streamed reads)
__device__ __nv_bfloat16 g_Ph[2][(size_t)NN * FH];
__device__ __nv_bfloat16 g_Pl[2][(size_t)NN * FH];
__device__ __nv_bfloat16 g_Q1h[(size_t)NN * FH];
__device__ __nv_bfloat16 g_Q1l[(size_t)NN * FH];
__device__ __nv_bfloat16 g_Q2h[(size_t)NN * FH];
__device__ __nv_bfloat16 g_Q2l[(size_t)NN * FH];
// int16 row-quantized gather planes (x ~= s_row * q)
__device__ unsigned short g_I0[2][(size_t)NN * FH];
__device__ float g_S0[2][NN];
__device__ unsigned short g_I1[(size_t)NN * FH];
__device__ float g_S1[NN];
// weights
__device__ __nv_bfloat16 g_Wth[6 * 128 * 384];   // W^T per layer: [n=128][k=384], hi
__device__ __nv_bfloat16 g_Wtl[6 * 128 * 384];   // lo

// ======================= helpers =======================
__device__ __forceinline__ uint32_t smem_u32(const void* p) {
    uint32_t a;
    asm("{ .reg .u64 t; cvta.to.shared.u64 t, %1; cvt.u32.u64 %0, t; }" : "=r"(a) : "l"(p));
    return a;
}

#define SWZ(off) ((off) ^ (((off) >> 3) & 0x70))

__device__ __forceinline__ void ldmx4(uint32_t* r, uint32_t addr) {
    asm volatile("ldmatrix.sync.aligned.m8n8.x4.shared.b16 {%0,%1,%2,%3}, [%4];"
                 : "=r"(r[0]), "=r"(r[1]), "=r"(r[2]), "=r"(r[3]) : "r"(addr));
}

__device__ __forceinline__ void mma_bf16(float* d, const uint32_t* a, const uint32_t* b) {
    asm volatile(
        "mma.sync.aligned.m16n8k16.row.col.f32.bf16.bf16.f32 "
        "{%0,%1,%2,%3}, {%4,%5,%6,%7}, {%8,%9}, {%0,%1,%2,%3};"
        : "+f"(d[0]), "+f"(d[1]), "+f"(d[2]), "+f"(d[3])
        : "r"(a[0]), "r"(a[1]), "r"(a[2]), "r"(a[3]), "r"(b[0]), "r"(b[1]));
}

__device__ __forceinline__ void cpa16(uint32_t saddr, const void* g, bool pred) {
    asm volatile("cp.async.cg.shared.global [%0], [%1], 16, %2;"
                 :: "r"(saddr), "l"(g), "r"(pred ? 16 : 0) : "memory");
}
#define CP_COMMIT() asm volatile("cp.async.commit_group;" ::: "memory")
#define CP_WAIT(n)  asm volatile("cp.async.wait_group %0;" :: "n"(n) : "memory")

__device__ __forceinline__ float blo(uint32_t u) { return __uint_as_float(u << 16); }
__device__ __forceinline__ float bhi(uint32_t u) { return __uint_as_float(u & 0xffff0000u); }

__device__ __forceinline__ uint32_t pack_hi2(float a, float b) {
    __nv_bfloat16 ha = __float2bfloat16(a), hb = __float2bfloat16(b);
    return (uint32_t)__bfloat16_as_ushort(ha) | ((uint32_t)__bfloat16_as_ushort(hb) << 16);
}
__device__ __forceinline__ uint32_t pack_lo2(float a, float b) {
    __nv_bfloat16 ha = __float2bfloat16(a), hb = __float2bfloat16(b);
    __nv_bfloat16 la = __float2bfloat16(a - __bfloat162float(ha));
    __nv_bfloat16 lb = __float2bfloat16(b - __bfloat162float(hb));
    return (uint32_t)__bfloat16_as_ushort(la) | ((uint32_t)__bfloat16_as_ushort(lb) << 16);
}
__device__ __forceinline__ uint32_t packs16(float a, float b, float sinv) {
    int qa = __float2int_rn(a * sinv);
    int qb = __float2int_rn(b * sinv);
    return ((uint32_t)qa & 0xffffu) | ((uint32_t)qb << 16);
}

// ======================= graph preprocessing =======================
__global__ void k_zero_deg() {
    int i = blockIdx.x * blockDim.x + threadIdx.x;
    if (i < NN) g_deg[i] = 0;
}
__global__ void k_hist(const int* __restrict__ dst) {
    int e = blockIdx.x * blockDim.x + threadIdx.x;
    if (e < NE) atomicAdd(&g_deg[dst[e]], 1);
}
__global__ void k_dinv() {
    int i = blockIdx.x * blockDim.x + threadIdx.x;
    if (i < NN) {
        int d = g_deg[i];
        float df = (float)(d > 1 ? d : 1);
        g_dinv[i] = rsqrtf(df);
        g_rdinv[i] = sqrtf(df);
    }
}

__global__ void __launch_bounds__(1024) k_scanA() {
    __shared__ int wsum[32];
    int t = threadIdx.x, lane = t & 31, wp = t >> 5;
    int i = blockIdx.x * 1024 + t;
    int v = (i < NN) ? g_deg[i] : 0;
    int x = v;
    #pragma unroll
    for (int o = 1; o < 32; o <<= 1) {
        int y = __shfl_up_sync(0xffffffffu, x, o);
        if (lane >= o) x += y;
    }
    if (lane == 31) wsum[wp] = x;
    __syncthreads();
    if (wp == 0) {
        int s = wsum[lane];
        #pragma unroll
        for (int o = 1; o < 32; o <<= 1) {
            int y = __shfl_up_sync(0xffffffffu, s, o);
            if (lane >= o) s += y;
        }
        wsum[lane] = s;
    }
    __syncthreads();
    int off = (wp ? wsum[wp - 1] : 0);
    if (i < NN) g_rowoff[i] = off + x - v;
    if (t == 1023) g_bsum[blockIdx.x] = wsum[31];
}

__global__ void k_scanB(int nb) {
    __shared__ int sh[4];
    int t = threadIdx.x, lane = t & 31, wp = t >> 5;
    int v = (t < nb) ? g_bsum[t] : 0;
    int x = v;
    #pragma unroll
    for (int o = 1; o < 32; o <<= 1) {
        int y = __shfl_up_sync(0xffffffffu, x, o);
        if (lane >= o) x += y;
    }
    if (lane == 31) sh[wp] = x;
    __syncthreads();
    int add = 0;
    for (int w = 0; w < wp; ++w) add += sh[w];
    if (t < 128) g_boff[t] = add + x - v;
}

__global__ void k_scanC() {
    int i = blockIdx.x * blockDim.x + threadIdx.x;
    if (i < NN) {
        int r = g_rowoff[i] + g_boff[i >> 10];
        g_rowoff[i] = r;
        g_cursor[i] = r;
    }
    if (i == 0) g_rowoff[NN] = NE;
}

__global__ void k_scatter(const int* __restrict__ src, const int* __restrict__ dst) {
    int e = blockIdx.x * blockDim.x + threadIdx.x;
    if (e < NE) {
        int p = atomicAdd(&g_cursor[dst[e]], 1);
        g_csr[p] = src[e];
    }
}

// ======================= input conversion (warp per row) =======================
__global__ void k_featsplit(const float* __restrict__ f) {
    int w = (blockIdx.x * blockDim.x + threadIdx.x) >> 5;
    int lane = threadIdx.x & 31;
    if (w >= NN) return;
    float dv = g_dinv[w];
    size_t base = (size_t)w * FH + lane * 4;
    float4 v = *(const float4*)(f + base);
    float p0 = v.x * dv, p1 = v.y * dv, p2 = v.z * dv, p3 = v.w * dv;
    uint2 h, l;
    h.x = pack_hi2(p0, p1); h.y = pack_hi2(p2, p3);
    l.x = pack_lo2(p0, p1); l.y = pack_lo2(p2, p3);
    *(uint2*)(&g_Ph[0][base]) = h;
    *(uint2*)(&g_Pl[0][base]) = l;
    float m = fmaxf(fmaxf(fabsf(p0), fabsf(p1)), fmaxf(fabsf(p2), fabsf(p3)));
    #pragma unroll
    for (int o = 16; o >= 1; o >>= 1) m = fmaxf(m, __shfl_xor_sync(0xffffffffu, m, o));
    float sinv = (m > 0.f) ? (32766.f / m) : 0.f;
    uint2 q;
    q.x = packs16(p0, p1, sinv);
    q.y = packs16(p2, p3, sinv);
    *(uint2*)(&g_I0[0][base]) = q;
    if (lane == 0) g_S0[0][w] = m * (1.f / 32766.f);
}

__global__ void k_prep_w(const float* __restrict__ W0, const float* __restrict__ Wh) {
    int i = blockIdx.x * blockDim.x + threadIdx.x;
    if (i >= 6 * 384 * 128) return;
    int l = i / (384 * 128);
    int r = i % (384 * 128);
    int k = r / 128, n = r % 128;
    const float* W = (l == 0) ? W0 : (Wh + (size_t)(l - 1) * 384 * 128);
    float v = W[(size_t)k * 128 + n];
    __nv_bfloat16 h = __float2bfloat16(v);
    float lo = v - __bfloat162float(h);
    size_t o = (size_t)l * 128 * 384 + (size_t)n * 384 + k;
    g_Wth[o] = h;
    g_Wtl[o] = __float2bfloat16(lo);
}

// ======================= SpMM: warp-per-node CSR gather over int16 planes ========
// Gathered rows: value = Ys[s] * q (int16). All planes prescaled by dinv.
// MODE 1: X1p = -dv^2 * sum ;  MODE 2: X2p = -2*dv^2 * sum - X0p[w]
// WI16: write int16+scale plane of result. WHL: write bf16 hi/lo planes.
template <int MODE, bool WI16, bool WHL>
__global__ void __launch_bounds__(256) k_spmm(
    const unsigned short* __restrict__ Yq, const float* __restrict__ Ys,
    const __nv_bfloat16* __restrict__ X0h_, const __nv_bfloat16* __restrict__ X0l_,
    unsigned short* __restrict__ oq, float* __restrict__ os,
    __nv_bfloat16* __restrict__ oh, __nv_bfloat16* __restrict__ ol) {
    int w = (blockIdx.x * blockDim.x + threadIdx.x) >> 5;
    int lane = threadIdx.x & 31;
    if (w >= NN) return;
    int beg = g_rowoff[w];
    int end = g_rowoff[w + 1];
    const size_t lo4 = (size_t)(lane * 4);
    float a0 = 0.f, a1 = 0.f, a2 = 0.f, a3 = 0.f;
    int i = beg;
    for (; i + 2 <= end; i += 2) {
        int s0 = g_csr[i], s1 = g_csr[i + 1];
        float c0 = Ys[s0], c1 = Ys[s1];
        uint2 u0 = *(const uint2*)(Yq + (size_t)s0 * FH + lo4);
        uint2 u1 = *(const uint2*)(Yq + (size_t)s1 * FH + lo4);
        a0 = fmaf((float)(short)u0.x, c0, a0);
        a1 = fmaf((float)((int)u0.x >> 16), c0, a1);
        a2 = fmaf((float)(short)u0.y, c0, a2);
        a3 = fmaf((float)((int)u0.y >> 16), c0, a3);
        a0 = fmaf((float)(short)u1.x, c1, a0);
        a1 = fmaf((float)((int)u1.x >> 16), c1, a1);
        a2 = fmaf((float)(short)u1.y, c1, a2);
        a3 = fmaf((float)((int)u1.y >> 16), c1, a3);
    }
    if (i < end) {
        int s0 = g_csr[i];
        float c0 = Ys[s0];
        uint2 u0 = *(const uint2*)(Yq + (size_t)s0 * FH + lo4);
        a0 = fmaf((float)(short)u0.x, c0, a0);
        a1 = fmaf((float)((int)u0.x >> 16), c0, a1);
        a2 = fmaf((float)(short)u0.y, c0, a2);
        a3 = fmaf((float)((int)u0.y >> 16), c0, a3);
    }
    float dv = g_dinv[w];
    float dv2 = dv * dv;
    float p0, p1, p2, p3;
    if (MODE == 1) {
        float m = -dv2;
        p0 = m * a0; p1 = m * a1; p2 = m * a2; p3 = m * a3;
    } else {
        size_t base = (size_t)w * FH + lo4;
        uint2 xh = *(const uint2*)(X0h_ + base);
        uint2 xl = *(const uint2*)(X0l_ + base);
        float m = -2.f * dv2;
        p0 = fmaf(m, a0, -(blo(xh.x) + blo(xl.x)));
        p1 = fmaf(m, a1, -(bhi(xh.x) + bhi(xl.x)));
        p2 = fmaf(m, a2, -(blo(xh.y) + blo(xl.y)));
        p3 = fmaf(m, a3, -(bhi(xh.y) + bhi(xl.y)));
    }
    size_t base = (size_t)w * FH + lo4;
    if (WHL) {
        uint2 h, l;
        h.x = pack_hi2(p0, p1); h.y = pack_hi2(p2, p3);
        l.x = pack_lo2(p0, p1); l.y = pack_lo2(p2, p3);
        *(uint2*)(oh + base) = h;
        *(uint2*)(ol + base) = l;
    }
    if (WI16) {
        float mx = fmaxf(fmaxf(fabsf(p0), fabsf(p1)), fmaxf(fabsf(p2), fabsf(p3)));
        #pragma unroll
        for (int o = 16; o >= 1; o >>= 1) mx = fmaxf(mx, __shfl_xor_sync(0xffffffffu, mx, o));
        float sinv = (mx > 0.f) ? (32766.f / mx) : 0.f;
        uint2 q;
        q.x = packs16(p0, p1, sinv);
        q.y = packs16(p2, p3, sinv);
        *(uint2*)(oq + base) = q;
        if (lane == 0) os[w] = mx * (1.f / 32766.f);
    }
}

// ======================= cp.async pipelined mma.sync bf16-pair GEMM ==============
// C = relu( rdinv[m] * ([X0p|X1p|X2p] @ W) + b ); p = C*dinv[m];
// store p as bf16 hi/lo planes + int16 row-quantized plane + row scale.
#define GM_A_HI 0
#define GM_A_LO 16384
#define GM_B_HI 32768
#define GM_B_LO 49152
#define GM_ST   65536
#define GM_SMEM_SZ (2 * GM_ST)

__device__ __forceinline__ void gm_load_chunk(
    uint32_t base, int kc, int rowBase, int tid,
    const __nv_bfloat16* __restrict__ ah, const __nv_bfloat16* __restrict__ al,
    const __nv_bfloat16* __restrict__ wth, const __nv_bfloat16* __restrict__ wtl) {
    const int coff = (kc & 1) * 64;
    #pragma unroll
    for (int t = 0; t < 2; ++t) {
        int idx = tid + t * 512;
        int r = idx >> 3, j = idx & 7;
        int row = rowBase + r;
        bool ok = row < NN;
        int rowc = ok ? row : (NN - 1);
        uint32_t sw = SWZ((uint32_t)(r * 128 + j * 16));
        cpa16(base + GM_A_HI + sw, ah + (size_t)rowc * FH + coff + j * 8, ok);
        cpa16(base + GM_A_LO + sw, al + (size_t)rowc * FH + coff + j * 8, ok);
    }
    #pragma unroll
    for (int t = 0; t < 2; ++t) {
        int idx = tid + t * 512;
        int n = idx >> 3, j = idx & 7;
        uint32_t sw = SWZ((uint32_t)(n * 128 + j * 16));
        cpa16(base + GM_B_HI + sw, wth + (size_t)n * 384 + kc * 64 + j * 8, true);
        cpa16(base + GM_B_LO + sw, wtl + (size_t)n * 384 + kc * 64 + j * 8, true);
    }
}

__global__ void __launch_bounds__(512) k_gemm_mma(
    const __nv_bfloat16* __restrict__ x0h, const __nv_bfloat16* __restrict__ x0l,
    const float* __restrict__ bias,
    const __nv_bfloat16* __restrict__ wth, const __nv_bfloat16* __restrict__ wtl,
    __nv_bfloat16* __restrict__ outh, __nv_bfloat16* __restrict__ outl,
    unsigned short* __restrict__ outq, float* __restrict__ outs) {
    extern __shared__ char smem_raw[];
    __shared__ float s_bias[128];
    __shared__ float s_rmax[128][4];
    uint32_t sb0 = smem_u32(smem_raw);
    uint32_t sb = (sb0 + 1023u) & ~1023u;          // 1024B-align for SW128

    const int tid = threadIdx.x, lane = tid & 31, wid = tid >> 5;
    const int wm = wid >> 2, wn = wid & 3;         // 4x4 warp grid
    const int rowBase = blockIdx.x * 128;
    if (tid < 128) s_bias[tid] = bias[tid];

    const __nv_bfloat16* Ah[3] = {x0h, g_Q1h, g_Q2h};
    const __nv_bfloat16* Al[3] = {x0l, g_Q1l, g_Q2l};

    float acc[2][4][4];
    #pragma unroll
    for (int a = 0; a < 2; ++a)
        #pragma unroll
        for (int b = 0; b < 4; ++b)
            #pragma unroll
            for (int c = 0; c < 4; ++c) acc[a][b][c] = 0.f;

    const int lrow = lane & 7, seg = lane >> 3;

    gm_load_chunk(sb, 0, rowBase, tid, Ah[0], Al[0], wth, wtl);
    CP_COMMIT();

    #pragma unroll 1
    for (int kc = 0; kc < 6; ++kc) {
        if (kc < 5) {
            int nk = kc + 1;
            gm_load_chunk(sb + ((nk & 1) ? GM_ST : 0), nk, rowBase, tid,
                          Ah[nk >> 1], Al[nk >> 1], wth, wtl);
            CP_COMMIT();
            CP_WAIT(1);
        } else {
            CP_WAIT(0);
        }
        __syncthreads();

        const uint32_t st = sb + ((kc & 1) ? GM_ST : 0);
        #pragma unroll
        for (int kt = 0; kt < 4; ++kt) {
            uint32_t Ahf[2][4], Alf[2][4], Bhf[2][4], Blf[2][4];
            #pragma unroll
            for (int mt = 0; mt < 2; ++mt) {
                int m = wm * 32 + mt * 16 + (seg & 1) * 8 + lrow;
                int kb = kt * 32 + (seg >> 1) * 16;
                uint32_t sw = SWZ((uint32_t)(m * 128 + kb));
                ldmx4(Ahf[mt], st + GM_A_HI + sw);
                ldmx4(Alf[mt], st + GM_A_LO + sw);
            }
            #pragma unroll
            for (int ntp = 0; ntp < 2; ++ntp) {
                int n = wn * 32 + ntp * 16 + (seg >> 1) * 8 + lrow;
                int kb = kt * 32 + (seg & 1) * 16;
                uint32_t sw = SWZ((uint32_t)(n * 128 + kb));
                ldmx4(Bhf[ntp], st + GM_B_HI + sw);
                ldmx4(Blf[ntp], st + GM_B_LO + sw);
            }
            #pragma unroll
            for (int mt = 0; mt < 2; ++mt)
                #pragma unroll
                for (int ntp = 0; ntp < 2; ++ntp)
                    #pragma unroll
                    for (int sub = 0; sub < 2; ++sub) {
                        int nj = ntp * 2 + sub;
                        mma_bf16(acc[mt][nj], Ahf[mt], &Bhf[ntp][sub * 2]);
                        mma_bf16(acc[mt][nj], Ahf[mt], &Blf[ntp][sub * 2]);
                        mma_bf16(acc[mt][nj], Alf[mt], &Bhf[ntp][sub * 2]);
                    }
        }
        __syncthreads();
    }

    // ---- epilogue ----
    float dvr[2][2], rdr[2][2];
    #pragma unroll
    for (int mt = 0; mt < 2; ++mt)
        #pragma unroll
        for (int rp = 0; rp < 2; ++rp) {
            int row = rowBase + wm * 32 + mt * 16 + (lane >> 2) + rp * 8;
            bool ok = row < NN;
            dvr[mt][rp] = ok ? g_dinv[row] : 0.f;
            rdr[mt][rp] = ok ? g_rdinv[row] : 0.f;
        }
    // pass 1: write hi/lo planes, track per-thread row max of p (p >= 0 after relu*dv)
    float pm[2][2] = {{0.f, 0.f}, {0.f, 0.f}};
    #pragma unroll
    for (int mt = 0; mt < 2; ++mt) {
        #pragma unroll
        for (int nj = 0; nj < 4; ++nj) {
            int col = wn * 32 + nj * 8 + (lane & 3) * 2;
            float bz0 = s_bias[col], bz1 = s_bias[col + 1];
            #pragma unroll
            for (int rp = 0; rp < 2; ++rp) {
                int row = rowBase + wm * 32 + mt * 16 + (lane >> 2) + rp * 8;
                float rd = rdr[mt][rp], dv = dvr[mt][rp];
                float p0 = fmaxf(fmaf(acc[mt][nj][rp * 2 + 0], rd, bz0), 0.f) * dv;
                float p1 = fmaxf(fmaf(acc[mt][nj][rp * 2 + 1], rd, bz1), 0.f) * dv;
                pm[mt][rp] = fmaxf(pm[mt][rp], fmaxf(p0, p1));
                if (row < NN) {
                    size_t base = (size_t)row * FH + col;
                    *(uint32_t*)(outh + base) = pack_hi2(p0, p1);
                    *(uint32_t*)(outl + base) = pack_lo2(p0, p1);
                }
            }
        }
    }
    // reduce row max over the 4 col-group lanes, stage per-warp result in smem
    #pragma unroll
    for (int mt = 0; mt < 2; ++mt)
        #pragma unroll
        for (int rp = 0; rp < 2; ++rp) {
            float m = pm[mt][rp];
            m = fmaxf(m, __shfl_xor_sync(0xffffffffu, m, 1));
            m = fmaxf(m, __shfl_xor_sync(0xffffffffu, m, 2));
            if ((lane & 3) == 0)
                s_rmax[wm * 32 + mt * 16 + rp * 8 + (lane >> 2)][wn] = m;
        }
    __syncthreads();
    // pass 2: quantize to int16 with cross-warp row max
    #pragma unroll
    for (int mt = 0; mt < 2; ++mt) {
        #pragma unroll
        for (int rp = 0; rp < 2; ++rp) {
            int rl = wm * 32 + mt * 16 + rp * 8 + (lane >> 2);
            int row = rowBase + rl;
            float rm = fmaxf(fmaxf(s_rmax[rl][0], s_rmax[rl][1]),
                             fmaxf(s_rmax[rl][2], s_rmax[rl][3]));
            float sinv = (rm > 0.f) ? (32766.f / rm) : 0.f;
            if (wn == 0 && (lane & 3) == 0 && row < NN)
                outs[row] = rm * (1.f / 32766.f);
            if (row < NN) {
                float rd = rdr[mt][rp], dv = dvr[mt][rp];
                #pragma unroll
                for (int nj = 0; nj < 4; ++nj) {
                    int col = wn * 32 + nj * 8 + (lane & 3) * 2;
                    float bz0 = s_bias[col], bz1 = s_bias[col + 1];
                    float p0 = fmaxf(fmaf(acc[mt][nj][rp * 2 + 0], rd, bz0), 0.f) * dv;
                    float p1 = fmaxf(fmaf(acc[mt][nj][rp * 2 + 1], rd, bz1), 0.f) * dv;
                    *(uint32_t*)(outq + (size_t)row * FH + col) = packs16(p0, p1, sinv);
                }
            }
        }
    }
}

// ======================= SIMT GEMM for final layer (CO=40) =======================
// All three bases reconstructed from prescaled hi/lo planes (* rdinv).
template <int CO, int TM, int TN>
__global__ void k_gemm_simt(
    const __nv_bfloat16* __restrict__ X0h_, const __nv_bfloat16* __restrict__ X0l_,
    const __nv_bfloat16* __restrict__ X1h_, const __nv_bfloat16* __restrict__ X1l_,
    const __nv_bfloat16* __restrict__ X2h_, const __nv_bfloat16* __restrict__ X2l_,
    const float* __restrict__ W, const float* __restrict__ bias,
    float* __restrict__ out) {
    constexpr int BM = 128, BK = 16;
    constexpr int NTX = CO / TN;
    constexpr int NTY = BM / TM;
    constexpr int NT = NTX * NTY;
    __shared__ float As[BK][BM + 1];
    __shared__ float Bs[BK][CO];
    const int tid = threadIdx.x;
    const int tx = tid % NTX;
    const int ty = tid / NTX;
    const int rowBase = blockIdx.x * BM;

    float acc[TM][TN];
    #pragma unroll
    for (int m = 0; m < TM; ++m)
        #pragma unroll
        for (int n = 0; n < TN; ++n) acc[m][n] = 0.f;

    #pragma unroll 1
    for (int kt = 0; kt < 24; ++kt) {
        const __nv_bfloat16* __restrict__ Xh = (kt < 8) ? X0h_ : ((kt < 16) ? X1h_ : X2h_);
        const __nv_bfloat16* __restrict__ Xl = (kt < 8) ? X0l_ : ((kt < 16) ? X1l_ : X2l_);
        const int kcol = (kt & 7) * BK;
        for (int i = tid; i < BM * BK; i += NT) {
            int r = i >> 4, k = i & 15;
            int row = rowBase + r;
            float v = 0.f;
            if (row < NN) {
                size_t off = (size_t)row * FH + kcol + k;
                uint32_t hu = (uint32_t)__bfloat16_as_ushort(Xh[off]) << 16;
                uint32_t lu = (uint32_t)__bfloat16_as_ushort(Xl[off]) << 16;
                v = (__uint_as_float(hu) + __uint_as_float(lu)) * g_rdinv[row];
            }
            As[k][r] = v;
        }
        for (int i = tid; i < BK * CO; i += NT) {
            int k = i / CO, c = i % CO;
            Bs[k][c] = W[(size_t)(kt * BK + k) * CO + c];
        }
        __syncthreads();
        #pragma unroll
        for (int k = 0; k < BK; ++k) {
            float ra[TM], rb[TN];
            #pragma unroll
            for (int m = 0; m < TM; ++m) ra[m] = As[k][ty * TM + m];
            #pragma unroll
            for (int n = 0; n < TN; ++n) rb[n] = Bs[k][tx * TN + n];
            #pragma unroll
            for (int m = 0; m < TM; ++m)
                #pragma unroll
                for (int n = 0; n < TN; ++n)
                    acc[m][n] = fmaf(ra[m], rb[n], acc[m][n]);
        }
        __syncthreads();
    }
    #pragma unroll
    for (int m = 0; m < TM; ++m) {
        int row = rowBase + ty * TM + m;
        if (row < NN) {
            #pragma unroll
            for (int n = 0; n < TN; ++n) {
                int c = tx * TN + n;
                out[(size_t)row * CO + c] = fmaxf(acc[m][n] + bias[c], 0.f);
            }
        }
    }
}

// ======================= host launcher =======================
extern "C" void kernel_launch(void* const* d_in, const int* in_sizes, int n_in,
                              void* d_out, int out_size) {
    const float* feat = (const float*)d_in[0];
    const int*   src  = (const int*)d_in[1];
    const int*   dst  = (const int*)d_in[2];
    const float* W0   = (const float*)d_in[3];
    const float* b0   = (const float*)d_in[4];
    const float* Wh   = (const float*)d_in[5];
    const float* bh   = (const float*)d_in[6];
    const float* Wl   = (const float*)d_in[7];
    const float* bl   = (const float*)d_in[8];
    float* out = (float*)d_out;

    __nv_bfloat16 *Ph, *Pl, *Q1h, *Q1l, *Q2h, *Q2l, *Wth, *Wtl;
    unsigned short *I0, *I1;
    float *S0, *S1;
    cudaGetSymbolAddress((void**)&Ph,  g_Ph);
    cudaGetSymbolAddress((void**)&Pl,  g_Pl);
    cudaGetSymbolAddress((void**)&Q1h, g_Q1h);
    cudaGetSymbolAddress((void**)&Q1l, g_Q1l);
    cudaGetSymbolAddress((void**)&Q2h, g_Q2h);
    cudaGetSymbolAddress((void**)&Q2l, g_Q2l);
    cudaGetSymbolAddress((void**)&I0,  g_I0);
    cudaGetSymbolAddress((void**)&I1,  g_I1);
    cudaGetSymbolAddress((void**)&S0,  g_S0);
    cudaGetSymbolAddress((void**)&S1,  g_S1);
    cudaGetSymbolAddress((void**)&Wth, g_Wth);
    cudaGetSymbolAddress((void**)&Wtl, g_Wtl);

    cudaFuncSetAttribute(k_gemm_mma, cudaFuncAttributeMaxDynamicSharedMemorySize,
                         GM_SMEM_SZ + 1024);

    const int TPB = 256;
    const int nodeBlocks = (NN + TPB - 1) / TPB;
    const int edgeBlocks = (NE + TPB - 1) / TPB;
    const int scanBlocks = (NN + 1023) / 1024;   // 98

    // preprocessing
    k_zero_deg<<<nodeBlocks, TPB>>>();
    k_hist<<<edgeBlocks, TPB>>>(dst);
    k_dinv<<<nodeBlocks, TPB>>>();
    k_scanA<<<scanBlocks, 1024>>>();
    k_scanB<<<1, 128>>>(scanBlocks);
    k_scanC<<<nodeBlocks, TPB>>>();
    k_scatter<<<edgeBlocks, TPB>>>(src, dst);

    // input conversion (warp per row)
    k_featsplit<<<(NN * 32 + TPB - 1) / TPB, TPB>>>(feat);
    k_prep_w<<<(6 * 384 * 128 + TPB - 1) / TPB, TPB>>>(W0, Wh);

    const size_t SL = (size_t)NN * FH;
    const int spmmBlocks = (NN * 32 + TPB - 1) / TPB;
    const int tileBlocks = (NN + 127) / 128;

    int cur = 0;
    for (int l = 0; l < 7; ++l) {
        const __nv_bfloat16* ch = Ph + (size_t)cur * SL;
        const __nv_bfloat16* cl = Pl + (size_t)cur * SL;
        // X1 = -S X0 : gather int16 X0; write int16+scale (for spmm2) and hi/lo planes
        k_spmm<1, true, true><<<spmmBlocks, TPB>>>(
            I0 + (size_t)cur * SL, S0 + (size_t)cur * NN,
            nullptr, nullptr, I1, S1, Q1h, Q1l);
        // X2 = -2 S X1 - X0 : gather int16 X1; write hi/lo planes only
        k_spmm<2, false, true><<<spmmBlocks, TPB>>>(
            I1, S1, ch, cl, nullptr, nullptr, Q2h, Q2l);
        if (l < 6) {
            const float* bias = (l == 0) ? b0 : (bh + (size_t)(l - 1) * 128);
            int nxt = 1 - cur;
            k_gemm_mma<<<tileBlocks, 512, GM_SMEM_SZ + 1024>>>(
                ch, cl, bias,
                Wth + (size_t)l * 128 * 384, Wtl + (size_t)l * 128 * 384,
                Ph + (size_t)nxt * SL, Pl + (size_t)nxt * SL,
                I0 + (size_t)nxt * SL, S0 + (size_t)nxt * NN);
            cur = nxt;
        } else {
            k_gemm_simt<FO, 8, 5><<<tileBlocks, 128>>>(
                ch, cl, Q1h, Q1l, Q2h, Q2l, Wl, bl, out);
        }
    }
}

// round 7
// speedup vs baseline: 1.8430x; 1.0194x over previous
#include <cuda_runtime.h>
#include <cuda_bf16.h>
#include <cstdint>

#define NN 100000
#define NE 1600000
#define FH 128
#define FO 40

// ======================= device scratch (no allocs allowed) =======================
__device__ int   g_deg[NN];
__device__ float g_dinv[NN];
__device__ float g_rdinv[NN];
__device__ int   g_rowoff[NN + 1];
__device__ int   g_cursor[NN];
__device__ int   g_csr[NE];
__device__ int   g_bsum[128];
__device__ int   g_boff[128];

// int16 row-quantized prescaled activation planes (x*dinv ~= s_row * q)
__device__ unsigned short g_I0[2][(size_t)NN * FH];
__device__ float g_S0[2][NN];
__device__ unsigned short g_I1[(size_t)NN * FH];
__device__ float g_S1[NN];
__device__ unsigned short g_I2[(size_t)NN * FH];
__device__ float g_S2[NN];
// weights (exact hi/lo bf16 split)
__device__ __nv_bfloat16 g_Wth[6 * 128 * 384];   // W^T per layer: [n=128][k=384], hi
__device__ __nv_bfloat16 g_Wtl[6 * 128 * 384];   // lo

// ======================= helpers =======================
__device__ __forceinline__ uint32_t smem_u32(const void* p) {
    uint32_t a;
    asm("{ .reg .u64 t; cvta.to.shared.u64 t, %1; cvt.u32.u64 %0, t; }" : "=r"(a) : "l"(p));
    return a;
}

#define SWZ(off) ((off) ^ (((off) >> 3) & 0x70))

__device__ __forceinline__ void ldmx4(uint32_t* r, uint32_t addr) {
    asm volatile("ldmatrix.sync.aligned.m8n8.x4.shared.b16 {%0,%1,%2,%3}, [%4];"
                 : "=r"(r[0]), "=r"(r[1]), "=r"(r[2]), "=r"(r[3]) : "r"(addr));
}

__device__ __forceinline__ void mma_bf16(float* d, const uint32_t* a, const uint32_t* b) {
    asm volatile(
        "mma.sync.aligned.m16n8k16.row.col.f32.bf16.bf16.f32 "
        "{%0,%1,%2,%3}, {%4,%5,%6,%7}, {%8,%9}, {%0,%1,%2,%3};"
        : "+f"(d[0]), "+f"(d[1]), "+f"(d[2]), "+f"(d[3])
        : "r"(a[0]), "r"(a[1]), "r"(a[2]), "r"(a[3]), "r"(b[0]), "r"(b[1]));
}

__device__ __forceinline__ void cpa16(uint32_t saddr, const void* g, bool pred) {
    asm volatile("cp.async.cg.shared.global [%0], [%1], 16, %2;"
                 :: "r"(saddr), "l"(g), "r"(pred ? 16 : 0) : "memory");
}
#define CP_COMMIT() asm volatile("cp.async.commit_group;" ::: "memory")
#define CP_WAIT(n)  asm volatile("cp.async.wait_group %0;" :: "n"(n) : "memory")

__device__ __forceinline__ uint32_t pack_hi2(float a, float b) {
    __nv_bfloat16 ha = __float2bfloat16(a), hb = __float2bfloat16(b);
    return (uint32_t)__bfloat16_as_ushort(ha) | ((uint32_t)__bfloat16_as_ushort(hb) << 16);
}
__device__ __forceinline__ uint32_t pack_lo2(float a, float b) {
    __nv_bfloat16 ha = __float2bfloat16(a), hb = __float2bfloat16(b);
    __nv_bfloat16 la = __float2bfloat16(a - __bfloat162float(ha));
    __nv_bfloat16 lb = __float2bfloat16(b - __bfloat162float(hb));
    return (uint32_t)__bfloat16_as_ushort(la) | ((uint32_t)__bfloat16_as_ushort(lb) << 16);
}
__device__ __forceinline__ uint32_t packs16(float a, float b, float sinv) {
    int qa = __float2int_rn(a * sinv);
    int qb = __float2int_rn(b * sinv);
    return ((uint32_t)qa & 0xffffu) | ((uint32_t)qb << 16);
}
__device__ __forceinline__ float slo(uint32_t u) { return (float)(short)(u & 0xffffu); }
__device__ __forceinline__ float shi(uint32_t u) { return (float)((int)u >> 16); }

// ======================= graph preprocessing =======================
__global__ void k_zero_deg() {
    int i = blockIdx.x * blockDim.x + threadIdx.x;
    if (i < NN) g_deg[i] = 0;
}
__global__ void k_hist(const int* __restrict__ dst) {
    int e = blockIdx.x * blockDim.x + threadIdx.x;
    if (e < NE) atomicAdd(&g_deg[dst[e]], 1);
}
__global__ void k_dinv() {
    int i = blockIdx.x * blockDim.x + threadIdx.x;
    if (i < NN) {
        int d = g_deg[i];
        float df = (float)(d > 1 ? d : 1);
        g_dinv[i] = rsqrtf(df);
        g_rdinv[i] = sqrtf(df);
    }
}

__global__ void __launch_bounds__(1024) k_scanA() {
    __shared__ int wsum[32];
    int t = threadIdx.x, lane = t & 31, wp = t >> 5;
    int i = blockIdx.x * 1024 + t;
    int v = (i < NN) ? g_deg[i] : 0;
    int x = v;
    #pragma unroll
    for (int o = 1; o < 32; o <<= 1) {
        int y = __shfl_up_sync(0xffffffffu, x, o);
        if (lane >= o) x += y;
    }
    if (lane == 31) wsum[wp] = x;
    __syncthreads();
    if (wp == 0) {
        int s = wsum[lane];
        #pragma unroll
        for (int o = 1; o < 32; o <<= 1) {
            int y = __shfl_up_sync(0xffffffffu, s, o);
            if (lane >= o) s += y;
        }
        wsum[lane] = s;
    }
    __syncthreads();
    int off = (wp ? wsum[wp - 1] : 0);
    if (i < NN) g_rowoff[i] = off + x - v;
    if (t == 1023) g_bsum[blockIdx.x] = wsum[31];
}

__global__ void k_scanB(int nb) {
    __shared__ int sh[4];
    int t = threadIdx.x, lane = t & 31, wp = t >> 5;
    int v = (t < nb) ? g_bsum[t] : 0;
    int x = v;
    #pragma unroll
    for (int o = 1; o < 32; o <<= 1) {
        int y = __shfl_up_sync(0xffffffffu, x, o);
        if (lane >= o) x += y;
    }
    if (lane == 31) sh[wp] = x;
    __syncthreads();
    int add = 0;
    for (int w = 0; w < wp; ++w) add += sh[w];
    if (t < 128) g_boff[t] = add + x - v;
}

__global__ void k_scanC() {
    int i = blockIdx.x * blockDim.x + threadIdx.x;
    if (i < NN) {
        int r = g_rowoff[i] + g_boff[i >> 10];
        g_rowoff[i] = r;
        g_cursor[i] = r;
    }
    if (i == 0) g_rowoff[NN] = NE;
}

__global__ void k_scatter(const int* __restrict__ src, const int* __restrict__ dst) {
    int e = blockIdx.x * blockDim.x + threadIdx.x;
    if (e < NE) {
        int p = atomicAdd(&g_cursor[dst[e]], 1);
        g_csr[p] = src[e];
    }
}

// ======================= input conversion (warp per row) =======================
__global__ void k_featsplit(const float* __restrict__ f) {
    int w = (blockIdx.x * blockDim.x + threadIdx.x) >> 5;
    int lane = threadIdx.x & 31;
    if (w >= NN) return;
    float dv = g_dinv[w];
    size_t base = (size_t)w * FH + lane * 4;
    float4 v = *(const float4*)(f + base);
    float p0 = v.x * dv, p1 = v.y * dv, p2 = v.z * dv, p3 = v.w * dv;
    float m = fmaxf(fmaxf(fabsf(p0), fabsf(p1)), fmaxf(fabsf(p2), fabsf(p3)));
    #pragma unroll
    for (int o = 16; o >= 1; o >>= 1) m = fmaxf(m, __shfl_xor_sync(0xffffffffu, m, o));
    float sinv = (m > 0.f) ? (32766.f / m) : 0.f;
    uint2 q;
    q.x = packs16(p0, p1, sinv);
    q.y = packs16(p2, p3, sinv);
    *(uint2*)(&g_I0[0][base]) = q;
    if (lane == 0) g_S0[0][w] = m * (1.f / 32766.f);
}

__global__ void k_prep_w(const float* __restrict__ W0, const float* __restrict__ Wh) {
    int i = blockIdx.x * blockDim.x + threadIdx.x;
    if (i >= 6 * 384 * 128) return;
    int l = i / (384 * 128);
    int r = i % (384 * 128);
    int k = r / 128, n = r % 128;
    const float* W = (l == 0) ? W0 : (Wh + (size_t)(l - 1) * 384 * 128);
    float v = W[(size_t)k * 128 + n];
    __nv_bfloat16 h = __float2bfloat16(v);
    float lo = v - __bfloat162float(h);
    size_t o = (size_t)l * 128 * 384 + (size_t)n * 384 + k;
    g_Wth[o] = h;
    g_Wtl[o] = __float2bfloat16(lo);
}

// ======================= SpMM: warp-per-node CSR gather, int16 in/out ============
// All planes prescaled by dinv. value = Ys[s] * q.
// MODE 1: X1p = -dv^2 * sum       MODE 2: X2p = -2*dv^2 * sum - X0p[w]
template <int MODE>
__global__ void __launch_bounds__(256) k_spmm(
    const unsigned short* __restrict__ Yq, const float* __restrict__ Ys,
    const unsigned short* __restrict__ X0q, const float* __restrict__ X0s,
    unsigned short* __restrict__ oq, float* __restrict__ os) {
    int w = (blockIdx.x * blockDim.x + threadIdx.x) >> 5;
    int lane = threadIdx.x & 31;
    if (w >= NN) return;
    int beg = g_rowoff[w];
    int end = g_rowoff[w + 1];
    const size_t lo4 = (size_t)(lane * 4);
    float a0 = 0.f, a1 = 0.f, a2 = 0.f, a3 = 0.f;
    int i = beg;
    for (; i + 4 <= end; i += 4) {
        int s0 = g_csr[i], s1 = g_csr[i + 1], s2 = g_csr[i + 2], s3 = g_csr[i + 3];
        float c0 = Ys[s0], c1 = Ys[s1], c2 = Ys[s2], c3 = Ys[s3];
        uint2 u0 = *(const uint2*)(Yq + (size_t)s0 * FH + lo4);
        uint2 u1 = *(const uint2*)(Yq + (size_t)s1 * FH + lo4);
        uint2 u2 = *(const uint2*)(Yq + (size_t)s2 * FH + lo4);
        uint2 u3 = *(const uint2*)(Yq + (size_t)s3 * FH + lo4);
        a0 = fmaf(slo(u0.x), c0, a0); a1 = fmaf(shi(u0.x), c0, a1);
        a2 = fmaf(slo(u0.y), c0, a2); a3 = fmaf(shi(u0.y), c0, a3);
        a0 = fmaf(slo(u1.x), c1, a0); a1 = fmaf(shi(u1.x), c1, a1);
        a2 = fmaf(slo(u1.y), c1, a2); a3 = fmaf(shi(u1.y), c1, a3);
        a0 = fmaf(slo(u2.x), c2, a0); a1 = fmaf(shi(u2.x), c2, a1);
        a2 = fmaf(slo(u2.y), c2, a2); a3 = fmaf(shi(u2.y), c2, a3);
        a0 = fmaf(slo(u3.x), c3, a0); a1 = fmaf(shi(u3.x), c3, a1);
        a2 = fmaf(slo(u3.y), c3, a2); a3 = fmaf(shi(u3.y), c3, a3);
    }
    for (; i < end; ++i) {
        int s0 = g_csr[i];
        float c0 = Ys[s0];
        uint2 u0 = *(const uint2*)(Yq + (size_t)s0 * FH + lo4);
        a0 = fmaf(slo(u0.x), c0, a0); a1 = fmaf(shi(u0.x), c0, a1);
        a2 = fmaf(slo(u0.y), c0, a2); a3 = fmaf(shi(u0.y), c0, a3);
    }
    float dv = g_dinv[w];
    float dv2 = dv * dv;
    float p0, p1, p2, p3;
    if (MODE == 1) {
        float m = -dv2;
        p0 = m * a0; p1 = m * a1; p2 = m * a2; p3 = m * a3;
    } else {
        float xs = X0s[w];
        uint2 xq = *(const uint2*)(X0q + (size_t)w * FH + lo4);
        float m = -2.f * dv2;
        p0 = fmaf(m, a0, -slo(xq.x) * xs);
        p1 = fmaf(m, a1, -shi(xq.x) * xs);
        p2 = fmaf(m, a2, -slo(xq.y) * xs);
        p3 = fmaf(m, a3, -shi(xq.y) * xs);
    }
    float mx = fmaxf(fmaxf(fabsf(p0), fabsf(p1)), fmaxf(fabsf(p2), fabsf(p3)));
    #pragma unroll
    for (int o = 16; o >= 1; o >>= 1) mx = fmaxf(mx, __shfl_xor_sync(0xffffffffu, mx, o));
    float sinv = (mx > 0.f) ? (32766.f / mx) : 0.f;
    uint2 q;
    q.x = packs16(p0, p1, sinv);
    q.y = packs16(p2, p3, sinv);
    *(uint2*)(oq + (size_t)w * FH + lo4) = q;
    if (lane == 0) os[w] = mx * (1.f / 32766.f);
}

// ======================= pipelined mma.sync GEMM, int16 A with smem dequant ======
// C = relu( rdinv[m] * ([X0p|X1p|X2p] @ W) + b ); p = C*dinv[m]; store int16+scale.
// Per stage: scratch(int16 A chunk) 16K | A_hi 16K | A_lo 16K | B_hi 16K | B_lo 16K.
#define GS_SCR 0
#define GS_AHI 16384
#define GS_ALO 32768
#define GS_BHI 49152
#define GS_BLO 65536
#define GS_ST  81920
#define GM_SMEM_SZ (2 * GS_ST)

__global__ void __launch_bounds__(512) k_gemm_mma(
    const unsigned short* __restrict__ x0q, const float* __restrict__ x0s,
    const float* __restrict__ bias,
    const __nv_bfloat16* __restrict__ wth, const __nv_bfloat16* __restrict__ wtl,
    unsigned short* __restrict__ outq, float* __restrict__ outs) {
    extern __shared__ char smem_raw[];
    __shared__ float s_bias[128];
    __shared__ float s_scl[3][128];
    __shared__ float s_rmax[128][4];
    uint32_t sb0 = smem_u32(smem_raw);
    uint32_t sb = (sb0 + 1023u) & ~1023u;          // 1024B-align for SW128
    char* smc = smem_raw + (sb - sb0);

    const int tid = threadIdx.x, lane = tid & 31, wid = tid >> 5;
    const int wm = wid >> 2, wn = wid & 3;         // 4x4 warp grid
    const int rowBase = blockIdx.x * 128;

    const unsigned short* Aq[3] = {x0q, g_I1, g_I2};
    const float* Sq[3] = {x0s, g_S1, g_S2};
    if (tid < 128) {
        s_bias[tid] = bias[tid];
        int row = rowBase + tid;
        bool ok = row < NN;
        #pragma unroll
        for (int b = 0; b < 3; ++b)
            s_scl[b][tid] = ok ? Sq[b][row] : 0.f;
    }
    __syncthreads();

    float acc[2][4][4];
    #pragma unroll
    for (int a = 0; a < 2; ++a)
        #pragma unroll
        for (int b = 0; b < 4; ++b)
            #pragma unroll
            for (int c = 0; c < 4; ++c) acc[a][b][c] = 0.f;

    const int lrow = lane & 7, seg = lane >> 3;

    // async load of chunk kc into stage: raw int16 A -> scratch, bf16 W -> B planes
    auto load_chunk = [&](uint32_t st, int kc) {
        const int coff = (kc & 1) * 64;
        const unsigned short* __restrict__ aq = Aq[kc >> 1];
        #pragma unroll
        for (int t = 0; t < 2; ++t) {
            int idx = tid + t * 512;
            int r = idx >> 3, j = idx & 7;
            int row = rowBase + r;
            bool ok = row < NN;
            int rowc = ok ? row : (NN - 1);
            cpa16(st + GS_SCR + (uint32_t)(r * 128 + j * 16),
                  aq + (size_t)rowc * FH + coff + j * 8, ok);
        }
        #pragma unroll
        for (int t = 0; t < 2; ++t) {
            int idx = tid + t * 512;
            int n = idx >> 3, j = idx & 7;
            uint32_t sw = SWZ((uint32_t)(n * 128 + j * 16));
            cpa16(st + GS_BHI + sw, wth + (size_t)n * 384 + kc * 64 + j * 8, true);
            cpa16(st + GS_BLO + sw, wtl + (size_t)n * 384 + kc * 64 + j * 8, true);
        }
    };

    load_chunk(sb, 0);
    CP_COMMIT();

    #pragma unroll 1
    for (int kc = 0; kc < 6; ++kc) {
        if (kc < 5) {
            load_chunk(sb + (((kc + 1) & 1) ? GS_ST : 0), kc + 1);
            CP_COMMIT();
            CP_WAIT(1);
        } else {
            CP_WAIT(0);
        }
        __syncthreads();

        const uint32_t st = sb + ((kc & 1) ? GS_ST : 0);
        char* stc = smc + ((kc & 1) ? GS_ST : 0);
        // dequant scratch int16 -> A hi/lo bf16 planes
        {
            const float* sc = s_scl[kc >> 1];
            #pragma unroll
            for (int t = 0; t < 2; ++t) {
                int idx = tid + t * 512;
                int r = idx >> 3, j = idx & 7;
                uint4 u = *(const uint4*)(stc + GS_SCR + (uint32_t)(r * 128 + j * 16));
                float s = sc[r];
                float v0 = slo(u.x) * s, v1 = shi(u.x) * s;
                float v2 = slo(u.y) * s, v3 = shi(u.y) * s;
                float v4 = slo(u.z) * s, v5 = shi(u.z) * s;
                float v6 = slo(u.w) * s, v7 = shi(u.w) * s;
                uint4 h, l;
                h.x = pack_hi2(v0, v1); l.x = pack_lo2(v0, v1);
                h.y = pack_hi2(v2, v3); l.y = pack_lo2(v2, v3);
                h.z = pack_hi2(v4, v5); l.z = pack_lo2(v4, v5);
                h.w = pack_hi2(v6, v7); l.w = pack_lo2(v6, v7);
                uint32_t sw = SWZ((uint32_t)(r * 128 + j * 16));
                *(uint4*)(stc + GS_AHI + sw) = h;
                *(uint4*)(stc + GS_ALO + sw) = l;
            }
        }
        __syncthreads();

        #pragma unroll
        for (int kt = 0; kt < 4; ++kt) {
            uint32_t Ahf[2][4], Alf[2][4], Bhf[2][4], Blf[2][4];
            #pragma unroll
            for (int mt = 0; mt < 2; ++mt) {
                int m = wm * 32 + mt * 16 + (seg & 1) * 8 + lrow;
                int kb = kt * 32 + (seg >> 1) * 16;
                uint32_t sw = SWZ((uint32_t)(m * 128 + kb));
                ldmx4(Ahf[mt], st + GS_AHI + sw);
                ldmx4(Alf[mt], st + GS_ALO + sw);
            }
            #pragma unroll
            for (int ntp = 0; ntp < 2; ++ntp) {
                int n = wn * 32 + ntp * 16 + (seg >> 1) * 8 + lrow;
                int kb = kt * 32 + (seg & 1) * 16;
                uint32_t sw = SWZ((uint32_t)(n * 128 + kb));
                ldmx4(Bhf[ntp], st + GS_BHI + sw);
                ldmx4(Blf[ntp], st + GS_BLO + sw);
            }
            #pragma unroll
            for (int mt = 0; mt < 2; ++mt)
                #pragma unroll
                for (int ntp = 0; ntp < 2; ++ntp)
                    #pragma unroll
                    for (int sub = 0; sub < 2; ++sub) {
                        int nj = ntp * 2 + sub;
                        mma_bf16(acc[mt][nj], Ahf[mt], &Bhf[ntp][sub * 2]);
                        mma_bf16(acc[mt][nj], Ahf[mt], &Blf[ntp][sub * 2]);
                        mma_bf16(acc[mt][nj], Alf[mt], &Bhf[ntp][sub * 2]);
                    }
        }
        __syncthreads();
    }

    // ---- epilogue: p = relu(acc*rdinv + b)*dinv; rowmax-quantize to int16 ----
    float dvr[2][2], rdr[2][2];
    #pragma unroll
    for (int mt = 0; mt < 2; ++mt)
        #pragma unroll
        for (int rp = 0; rp < 2; ++rp) {
            int row = rowBase + wm * 32 + mt * 16 + (lane >> 2) + rp * 8;
            bool ok = row < NN;
            dvr[mt][rp] = ok ? g_dinv[row] : 0.f;
            rdr[mt][rp] = ok ? g_rdinv[row] : 0.f;
        }
    // pass 1: per-thread row max of p
    float pm[2][2] = {{0.f, 0.f}, {0.f, 0.f}};
    #pragma unroll
    for (int mt = 0; mt < 2; ++mt)
        #pragma unroll
        for (int nj = 0; nj < 4; ++nj) {
            int col = wn * 32 + nj * 8 + (lane & 3) * 2;
            float bz0 = s_bias[col], bz1 = s_bias[col + 1];
            #pragma unroll
            for (int rp = 0; rp < 2; ++rp) {
                float rd = rdr[mt][rp], dv = dvr[mt][rp];
                float p0 = fmaxf(fmaf(acc[mt][nj][rp * 2 + 0], rd, bz0), 0.f) * dv;
                float p1 = fmaxf(fmaf(acc[mt][nj][rp * 2 + 1], rd, bz1), 0.f) * dv;
                pm[mt][rp] = fmaxf(pm[mt][rp], fmaxf(p0, p1));
            }
        }
    #pragma unroll
    for (int mt = 0; mt < 2; ++mt)
        #pragma unroll
        for (int rp = 0; rp < 2; ++rp) {
            float m = pm[mt][rp];
            m = fmaxf(m, __shfl_xor_sync(0xffffffffu, m, 1));
            m = fmaxf(m, __shfl_xor_sync(0xffffffffu, m, 2));
            if ((lane & 3) == 0)
                s_rmax[wm * 32 + mt * 16 + rp * 8 + (lane >> 2)][wn] = m;
        }
    __syncthreads();
    // pass 2: quantize + write
    #pragma unroll
    for (int mt = 0; mt < 2; ++mt)
        #pragma unroll
        for (int rp = 0; rp < 2; ++rp) {
            int rl = wm * 32 + mt * 16 + rp * 8 + (lane >> 2);
            int row = rowBase + rl;
            float rm = fmaxf(fmaxf(s_rmax[rl][0], s_rmax[rl][1]),
                             fmaxf(s_rmax[rl][2], s_rmax[rl][3]));
            float sinv = (rm > 0.f) ? (32766.f / rm) : 0.f;
            if (wn == 0 && (lane & 3) == 0 && row < NN)
                outs[row] = rm * (1.f / 32766.f);
            if (row < NN) {
                float rd = rdr[mt][rp], dv = dvr[mt][rp];
                #pragma unroll
                for (int nj = 0; nj < 4; ++nj) {
                    int col = wn * 32 + nj * 8 + (lane & 3) * 2;
                    float bz0 = s_bias[col], bz1 = s_bias[col + 1];
                    float p0 = fmaxf(fmaf(acc[mt][nj][rp * 2 + 0], rd, bz0), 0.f) * dv;
                    float p1 = fmaxf(fmaf(acc[mt][nj][rp * 2 + 1], rd, bz1), 0.f) * dv;
                    *(uint32_t*)(outq + (size_t)row * FH + col) = packs16(p0, p1, sinv);
                }
            }
        }
}

// ======================= SIMT GEMM for final layer (CO=40) =======================
// bases reconstructed from int16 planes: x = q * s_row * rdinv.
template <int CO, int TM, int TN>
__global__ void k_gemm_simt(
    const unsigned short* __restrict__ X0q, const float* __restrict__ X0s,
    const unsigned short* __restrict__ X1q, const float* __restrict__ X1s,
    const unsigned short* __restrict__ X2q, const float* __restrict__ X2s,
    const float* __restrict__ W, const float* __restrict__ bias,
    float* __restrict__ out) {
    constexpr int BM = 128, BK = 16;
    constexpr int NTX = CO / TN;
    constexpr int NTY = BM / TM;
    constexpr int NT = NTX * NTY;
    __shared__ float As[BK][BM + 1];
    __shared__ float Bs[BK][CO];
    const int tid = threadIdx.x;
    const int tx = tid % NTX;
    const int ty = tid / NTX;
    const int rowBase = blockIdx.x * BM;

    float acc[TM][TN];
    #pragma unroll
    for (int m = 0; m < TM; ++m)
        #pragma unroll
        for (int n = 0; n < TN; ++n) acc[m][n] = 0.f;

    #pragma unroll 1
    for (int kt = 0; kt < 24; ++kt) {
        const unsigned short* __restrict__ Xq = (kt < 8) ? X0q : ((kt < 16) ? X1q : X2q);
        const float* __restrict__ Xs = (kt < 8) ? X0s : ((kt < 16) ? X1s : X2s);
        const int kcol = (kt & 7) * BK;
        for (int i = tid; i < BM * BK; i += NT) {
            int r = i >> 4, k = i & 15;
            int row = rowBase + r;
            float v = 0.f;
            if (row < NN) {
                size_t off = (size_t)row * FH + kcol + k;
                v = (float)(short)Xq[off] * Xs[row] * g_rdinv[row];
            }
            As[k][r] = v;
        }
        for (int i = tid; i < BK * CO; i += NT) {
            int k = i / CO, c = i % CO;
            Bs[k][c] = W[(size_t)(kt * BK + k) * CO + c];
        }
        __syncthreads();
        #pragma unroll
        for (int k = 0; k < BK; ++k) {
            float ra[TM], rb[TN];
            #pragma unroll
            for (int m = 0; m < TM; ++m) ra[m] = As[k][ty * TM + m];
            #pragma unroll
            for (int n = 0; n < TN; ++n) rb[n] = Bs[k][tx * TN + n];
            #pragma unroll
            for (int m = 0; m < TM; ++m)
                #pragma unroll
                for (int n = 0; n < TN; ++n)
                    acc[m][n] = fmaf(ra[m], rb[n], acc[m][n]);
        }
        __syncthreads();
    }
    #pragma unroll
    for (int m = 0; m < TM; ++m) {
        int row = rowBase + ty * TM + m;
        if (row < NN) {
            #pragma unroll
            for (int n = 0; n < TN; ++n) {
                int c = tx * TN + n;
                out[(size_t)row * CO + c] = fmaxf(acc[m][n] + bias[c], 0.f);
            }
        }
    }
}

// ======================= host launcher =======================
extern "C" void kernel_launch(void* const* d_in, const int* in_sizes, int n_in,
                              void* d_out, int out_size) {
    const float* feat = (const float*)d_in[0];
    const int*   src  = (const int*)d_in[1];
    const int*   dst  = (const int*)d_in[2];
    const float* W0   = (const float*)d_in[3];
    const float* b0   = (const float*)d_in[4];
    const float* Wh   = (const float*)d_in[5];
    const float* bh   = (const float*)d_in[6];
    const float* Wl   = (const float*)d_in[7];
    const float* bl   = (const float*)d_in[8];
    float* out = (float*)d_out;

    unsigned short *I0, *I1, *I2;
    float *S0, *S1, *S2;
    __nv_bfloat16 *Wth, *Wtl;
    cudaGetSymbolAddress((void**)&I0,  g_I0);
    cudaGetSymbolAddress((void**)&I1,  g_I1);
    cudaGetSymbolAddress((void**)&I2,  g_I2);
    cudaGetSymbolAddress((void**)&S0,  g_S0);
    cudaGetSymbolAddress((void**)&S1,  g_S1);
    cudaGetSymbolAddress((void**)&S2,  g_S2);
    cudaGetSymbolAddress((void**)&Wth, g_Wth);
    cudaGetSymbolAddress((void**)&Wtl, g_Wtl);

    cudaFuncSetAttribute(k_gemm_mma, cudaFuncAttributeMaxDynamicSharedMemorySize,
                         GM_SMEM_SZ + 1024);

    const int TPB = 256;
    const int nodeBlocks = (NN + TPB - 1) / TPB;
    const int edgeBlocks = (NE + TPB - 1) / TPB;
    const int scanBlocks = (NN + 1023) / 1024;   // 98

    // preprocessing
    k_zero_deg<<<nodeBlocks, TPB>>>();
    k_hist<<<edgeBlocks, TPB>>>(dst);
    k_dinv<<<nodeBlocks, TPB>>>();
    k_scanA<<<scanBlocks, 1024>>>();
    k_scanB<<<1, 128>>>(scanBlocks);
    k_scanC<<<nodeBlocks, TPB>>>();
    k_scatter<<<edgeBlocks, TPB>>>(src, dst);

    // input conversion (warp per row)
    k_featsplit<<<(NN * 32 + TPB - 1) / TPB, TPB>>>(feat);
    k_prep_w<<<(6 * 384 * 128 + TPB - 1) / TPB, TPB>>>(W0, Wh);

    const size_t SL = (size_t)NN * FH;
    const int spmmBlocks = (NN * 32 + TPB - 1) / TPB;
    const int tileBlocks = (NN + 127) / 128;

    int cur = 0;
    for (int l = 0; l < 7; ++l) {
        const unsigned short* I0c = I0 + (size_t)cur * SL;
        const float* S0c = S0 + (size_t)cur * NN;
        k_spmm<1><<<spmmBlocks, TPB>>>(I0c, S0c, nullptr, nullptr, I1, S1);
        k_spmm<2><<<spmmBlocks, TPB>>>(I1, S1, I0c, S0c, I2, S2);
        if (l < 6) {
            const float* bias = (l == 0) ? b0 : (bh + (size_t)(l - 1) * 128);
            int nxt = 1 - cur;
            k_gemm_mma<<<tileBlocks, 512, GM_SMEM_SZ + 1024>>>(
                I0c, S0c, bias,
                Wth + (size_t)l * 128 * 384, Wtl + (size_t)l * 128 * 384,
                I0 + (size_t)nxt * SL, S0 + (size_t)nxt * NN);
            cur = nxt;
        } else {
            k_gemm_simt<FO, 8, 5><<<tileBlocks, 128>>>(
                I0c, S0c, I1, S1, I2, S2, Wl, bl, out);
        }
    }
}